// round 11
// baseline (speedup 1.0000x reference)
#include <cuda_runtime.h>
#include <math.h>
#include <stdint.h>

// Problem constants
#define Bz 8
#define Sz 1024
#define Dz 1024
#define Hz 16
#define Mz (Bz*Sz)          // 8192 rows
#define BHz (Bz*Hz)         // 128 (b,h) pairs

// ---------------- scratch (device globals: no allocation allowed) ----------------
__device__ float g_q[Mz*Dz];
__device__ float g_k[Mz*Dz];
__device__ float g_v[Mz*Dz];
__device__ float g_vatt[Mz*Dz];
__device__ float g_X[Mz*Dz];
__device__ float g_xr[Mz*Dz];
__device__ float g_qr[Mz*Dz];
__device__ float g_h1[Mz*Dz];       // FFN hidden; also temp rounded-K before attention
__device__ float g_t[Mz*Dz];        // GEMM temp; also temp rounded-V before attention
__device__ float g_wr[6*Dz*Dz];     // pre-rounded weights: Wq Wk Wv Wo w1 w2
__device__ float g_attfb[134217728];

__device__ __forceinline__ float gelu_exact(float x) {
    return 0.5f * x * (1.0f + erff(x * 0.70710678118654752f));
}

__device__ __forceinline__ float tf32r(float x) {
    uint32_t u;
    asm("cvt.rna.tf32.f32 %0, %1;" : "=r"(u) : "f"(x));
    return __uint_as_float(u);
}

__device__ __forceinline__ void mma8(float* c, const uint32_t* a, uint32_t b0, uint32_t b1) {
    asm("mma.sync.aligned.m16n8k8.row.col.f32.tf32.tf32.f32 "
        "{%0,%1,%2,%3}, {%4,%5,%6,%7}, {%8,%9}, {%0,%1,%2,%3};"
        : "+f"(c[0]), "+f"(c[1]), "+f"(c[2]), "+f"(c[3])
        : "r"(a[0]), "r"(a[1]), "r"(a[2]), "r"(a[3]), "r"(b0), "r"(b1));
}

__device__ __forceinline__ void cpa16(uint32_t s, const void* g) {
    asm volatile("cp.async.ca.shared.global [%0], [%1], 16;\n" :: "r"(s), "l"(g));
}

// ---------------- batched tf32 round-copy (grid.y = segment) ----------------
__global__ void roundcopy3(const float4* __restrict__ s0, const float4* __restrict__ s1,
                           const float4* __restrict__ s2,
                           float4* __restrict__ d0, float4* __restrict__ d1,
                           float4* __restrict__ d2)
{
    int i = blockIdx.x * blockDim.x + threadIdx.x;
    const float4* s = (blockIdx.y == 0) ? s0 : (blockIdx.y == 1) ? s1 : s2;
    float4* d = (blockIdx.y == 0) ? d0 : (blockIdx.y == 1) ? d1 : d2;
    float4 v = s[i];
    float4 t;
    t.x = tf32r(v.x); t.y = tf32r(v.y); t.z = tf32r(v.z); t.w = tf32r(v.w);
    d[i] = t;
}

// seg is the per-matrix stride IN FLOAT4 UNITS (Dz*Dz/4).
__global__ void roundcopy6(const float4* __restrict__ s0, const float4* __restrict__ s1,
                           const float4* __restrict__ s2, const float4* __restrict__ s3,
                           const float4* __restrict__ s4, const float4* __restrict__ s5,
                           float4* __restrict__ dst, int seg)
{
    int i = blockIdx.x * blockDim.x + threadIdx.x;
    const float4* s;
    switch (blockIdx.y) {
        case 0: s = s0; break; case 1: s = s1; break; case 2: s = s2; break;
        case 3: s = s3; break; case 4: s = s4; break; default: s = s5; break;
    }
    float4 v = s[i];
    float4 t;
    t.x = tf32r(v.x); t.y = tf32r(v.y); t.z = tf32r(v.z); t.w = tf32r(v.w);
    dst[(size_t)blockIdx.y * seg + i] = t;
}

// ---------------- tf32 tensor-core GEMM body (cp.async 2-stage, k32) ----------------
// ROUND-7 PROVEN CORE (115us/GEMM measured). Inputs pre-rounded to tf32.
// A: [M,K] row-major. TB=false: B [K,N] (NN). TB=true: B [N,K] (NT, C = A@B^T).
// 128x128x32 tiles, 256 threads (8 warps 2x4), warp tile 64x32 via m16n8k8.
#define ASTG 4608            // 128*36 floats per stage
template<bool TB, int EPI, bool RND>   // EPI: 0 none, 1 bias+gelu, 2 bias
__device__ __forceinline__ void gemm_body(
    const float* __restrict__ A, const float* __restrict__ Bm,
    const float* __restrict__ bias, float* __restrict__ C,
    int M, int N, int K)
{
    constexpr int BSTG = TB ? 4608 : 4352;   // [n][k]s36 : [k][n]s136
    extern __shared__ float sh[];
    float* As = sh;
    float* Bs = sh + 2 * ASTG;

    const int tid = threadIdx.x;
    const int lane = tid & 31, warp = tid >> 5;
    const int wm = (warp >> 2) * 64, wn = (warp & 3) * 32;
    const int g = lane >> 2, tg = lane & 3;
    const int bx = blockIdx.x * 128, by = blockIdx.y * 128;

    const uint32_t sa = (uint32_t)__cvta_generic_to_shared(As);
    const uint32_t sb = (uint32_t)__cvta_generic_to_shared(Bs);

    float acc[4][4][4];
    #pragma unroll
    for (int mi = 0; mi < 4; mi++)
        #pragma unroll
        for (int ni = 0; ni < 4; ni++)
            #pragma unroll
            for (int q = 0; q < 4; q++) acc[mi][ni][q] = 0.0f;

    int ar[4], ac[4], br[4], bc[4];
    #pragma unroll
    for (int u = 0; u < 4; u++) {
        int f = tid + u * 256;
        ar[u] = f >> 3; ac[u] = (f & 7) * 4;               // A: 128 rows x 8 chunks
        if (TB) { br[u] = f >> 3; bc[u] = (f & 7) * 4; }   // B: 128 rows x 8 chunks
        else    { br[u] = f >> 5; bc[u] = (f & 31) * 4; }  // B: 32 rows x 32 chunks
    }

    const int nk = K >> 5;

    // prologue: stage 0
    {
        #pragma unroll
        for (int u = 0; u < 4; u++)
            cpa16(sa + (uint32_t)(ar[u] * 36 + ac[u]) * 4,
                  &A[(size_t)(by + ar[u]) * K + ac[u]]);
        if (TB) {
            #pragma unroll
            for (int u = 0; u < 4; u++)
                cpa16(sb + (uint32_t)(br[u] * 36 + bc[u]) * 4,
                      &Bm[(size_t)(bx + br[u]) * K + bc[u]]);
        } else {
            #pragma unroll
            for (int u = 0; u < 4; u++)
                cpa16(sb + (uint32_t)(br[u] * 136 + bc[u]) * 4,
                      &Bm[(size_t)(br[u]) * N + bx + bc[u]]);
        }
        asm volatile("cp.async.commit_group;\n" ::);
    }

    for (int kt = 0; kt < nk; kt++) {
        const int p = kt & 1;
        if (kt + 1 < nk) {
            const int ko = (kt + 1) * 32;
            const uint32_t pa = sa + (uint32_t)(((kt + 1) & 1) * ASTG) * 4;
            const uint32_t pb = sb + (uint32_t)(((kt + 1) & 1) * BSTG) * 4;
            #pragma unroll
            for (int u = 0; u < 4; u++)
                cpa16(pa + (uint32_t)(ar[u] * 36 + ac[u]) * 4,
                      &A[(size_t)(by + ar[u]) * K + ko + ac[u]]);
            if (TB) {
                #pragma unroll
                for (int u = 0; u < 4; u++)
                    cpa16(pb + (uint32_t)(br[u] * 36 + bc[u]) * 4,
                          &Bm[(size_t)(bx + br[u]) * K + ko + bc[u]]);
            } else {
                #pragma unroll
                for (int u = 0; u < 4; u++)
                    cpa16(pb + (uint32_t)(br[u] * 136 + bc[u]) * 4,
                          &Bm[(size_t)(ko + br[u]) * N + bx + bc[u]]);
            }
            asm volatile("cp.async.commit_group;\n" ::);
            asm volatile("cp.async.wait_group 1;\n" ::);
        } else {
            asm volatile("cp.async.wait_group 0;\n" ::);
        }
        __syncthreads();

        const float* Ap = As + p * ASTG;
        const float* Bp = Bs + p * BSTG;
        #pragma unroll
        for (int k8 = 0; k8 < 32; k8 += 8) {
            uint32_t af[4][4];
            #pragma unroll
            for (int mi = 0; mi < 4; mi++) {
                const int r0 = (wm + mi * 16 + g) * 36 + k8 + tg;
                af[mi][0] = __float_as_uint(Ap[r0]);
                af[mi][1] = __float_as_uint(Ap[r0 + 8 * 36]);
                af[mi][2] = __float_as_uint(Ap[r0 + 4]);
                af[mi][3] = __float_as_uint(Ap[r0 + 8 * 36 + 4]);
            }
            #pragma unroll
            for (int ni = 0; ni < 4; ni++) {
                const int c0 = wn + ni * 8 + g;
                uint32_t b0, b1;
                if (TB) {
                    b0 = __float_as_uint(Bp[c0 * 36 + k8 + tg]);
                    b1 = __float_as_uint(Bp[c0 * 36 + k8 + 4 + tg]);
                } else {
                    b0 = __float_as_uint(Bp[(k8 + tg) * 136 + c0]);
                    b1 = __float_as_uint(Bp[(k8 + 4 + tg) * 136 + c0]);
                }
                #pragma unroll
                for (int mi = 0; mi < 4; mi++) mma8(acc[mi][ni], af[mi], b0, b1);
            }
        }
        __syncthreads();
    }

    #pragma unroll
    for (int mi = 0; mi < 4; mi++) {
        const int r0 = by + wm + mi * 16 + g;
        #pragma unroll
        for (int ni = 0; ni < 4; ni++) {
            const int c0 = bx + wn + ni * 8 + 2 * tg;
            float v0 = acc[mi][ni][0], v1 = acc[mi][ni][1];
            float v2 = acc[mi][ni][2], v3 = acc[mi][ni][3];
            if (EPI != 0) {
                float bb0 = bias[c0], bb1 = bias[c0 + 1];
                v0 += bb0; v1 += bb1; v2 += bb0; v3 += bb1;
            }
            if (EPI == 1) {
                v0 = gelu_exact(v0); v1 = gelu_exact(v1);
                v2 = gelu_exact(v2); v3 = gelu_exact(v3);
            }
            if (RND) {
                v0 = tf32r(v0); v1 = tf32r(v1); v2 = tf32r(v2); v3 = tf32r(v3);
            }
            float2 w0; w0.x = v0; w0.y = v1;
            float2 w1; w1.x = v2; w1.y = v3;
            *(float2*)&C[(size_t)r0 * N + c0] = w0;
            *(float2*)&C[(size_t)(r0 + 8) * N + c0] = w1;
        }
    }
}

template<bool TB, int EPI, bool RND>
__global__ __launch_bounds__(256, 2)
void tgemm2(const float* __restrict__ A, const float* __restrict__ Bm,
            const float* __restrict__ bias, float* __restrict__ C,
            int M, int N, int K)
{
    gemm_body<TB, EPI, RND>(A, Bm, bias, C, M, N, K);
}

// merged QKV: grid.z in {0,1,2} selects (A,B,C) triple. NN, no epi, rounded out.
__global__ __launch_bounds__(256, 2)
void qkv_gemm(const float* __restrict__ A0, const float* __restrict__ A1,
              const float* __restrict__ A2,
              const float* __restrict__ B0, const float* __restrict__ B1,
              const float* __restrict__ B2,
              float* __restrict__ C0, float* __restrict__ C1, float* __restrict__ C2,
              int M, int N, int K)
{
    const float* A = (blockIdx.z == 0) ? A0 : (blockIdx.z == 1) ? A1 : A2;
    const float* B = (blockIdx.z == 0) ? B0 : (blockIdx.z == 1) ? B1 : B2;
    float*       C = (blockIdx.z == 0) ? C0 : (blockIdx.z == 1) ? C1 : C2;
    gemm_body<false, 0, true>(A, B, nullptr, C, M, N, K);
}

// ---------------- fused tensor-core flash attention (unchanged, known good) ----------------
#define AT_SMEM 107520
__global__ __launch_bounds__(256, 2)
void attn_fused(const float* __restrict__ qp, const float* __restrict__ kp,
                const float* __restrict__ vp, float* __restrict__ att,
                float* __restrict__ vatt)
{
    extern __shared__ float sh[];
    float* Qs   = sh;                    // [128][68]
    float* Ks   = sh + 128 * 68;         // [64][68]
    float* Vs   = Ks + 64 * 68;          // [64][68]
    float* Ps   = Vs + 64 * 68;          // [128][68]
    float* smP  = Ps + 128 * 68;         // [128][4]
    float* sm_m = smP + 512;             // [128]
    float* sm_il= sm_m + 128;            // [128]

    const int bh = blockIdx.x, b = bh >> 4, h = bh & 15;
    const int qt = 7 - blockIdx.y;
    const int qbase = qt * 128;
    const int tid = threadIdx.x;
    const int lane = tid & 31, warp = tid >> 5;
    const int wy = warp >> 1, wx = warp & 1;
    const int wm = wy * 32;
    const int g = lane >> 2, tg = lane & 3;
    const float scale = 1.0f / (8.0f + 1e-6f);

    const float* qg = qp + ((size_t)(b * Sz + qbase)) * Dz + h * 64;
    #pragma unroll
    for (int u = 0; u < 8; u++) {
        int f = tid + u * 256;
        int r = f >> 4, c4 = (f & 15) * 4;
        *(float4*)&Qs[r * 68 + c4] = *(const float4*)&qg[(size_t)r * Dz + c4];
    }

    float* ab = att + (size_t)bh * Sz * Sz;
    {
        float4 z; z.x = z.y = z.z = z.w = 0.0f;
        for (int j2 = 2 * qt + 2; j2 < 16; j2++) {
            const int kb = j2 * 64;
            #pragma unroll
            for (int u = 0; u < 8; u++) {
                int f = tid + u * 256;
                int r = f >> 4, c4 = (f & 15) * 4;
                *(float4*)&ab[(size_t)(qbase + r) * Sz + kb + c4] = z;
            }
        }
    }

    const int jmax = 2 * qt + 1;
    float run_m[4], run_l[4];
    #pragma unroll
    for (int s = 0; s < 4; s++) { run_m[s] = -1e30f; run_l[s] = 0.0f; }

    // ---------------- phase 1: softmax stats ----------------
    for (int jt = 0; jt <= jmax; jt++) {
        const int kbase = jt * 64;
        __syncthreads();
        const float* kg = kp + ((size_t)(b * Sz + kbase)) * Dz + h * 64;
        #pragma unroll
        for (int u = 0; u < 4; u++) {
            int f = tid + u * 256;
            int r = f >> 4, c4 = (f & 15) * 4;
            *(float4*)&Ks[r * 68 + c4] = *(const float4*)&kg[(size_t)r * Dz + c4];
        }
        __syncthreads();

        float sacc[2][4][4];
        #pragma unroll
        for (int mi = 0; mi < 2; mi++)
            #pragma unroll
            for (int ni = 0; ni < 4; ni++)
                #pragma unroll
                for (int q = 0; q < 4; q++) sacc[mi][ni][q] = 0.0f;

        #pragma unroll
        for (int k8 = 0; k8 < 64; k8 += 8) {
            uint32_t af[2][4];
            #pragma unroll
            for (int mi = 0; mi < 2; mi++) {
                const int r0 = (wm + mi * 16 + g) * 68 + k8 + tg;
                af[mi][0] = __float_as_uint(Qs[r0]);
                af[mi][1] = __float_as_uint(Qs[r0 + 8 * 68]);
                af[mi][2] = __float_as_uint(Qs[r0 + 4]);
                af[mi][3] = __float_as_uint(Qs[r0 + 8 * 68 + 4]);
            }
            #pragma unroll
            for (int ni = 0; ni < 4; ni++) {
                const int cb = (wx * 32 + ni * 8 + g) * 68 + k8 + tg;
                uint32_t b0 = __float_as_uint(Ks[cb]);
                uint32_t b1 = __float_as_uint(Ks[cb + 4]);
                mma8(sacc[0][ni], af[0], b0, b1);
                mma8(sacc[1][ni], af[1], b0, b1);
            }
        }

        const bool msk = (jt >= 2 * qt);
        #pragma unroll
        for (int mi = 0; mi < 2; mi++) {
            #pragma unroll
            for (int hf = 0; hf < 2; hf++) {
                const int s = mi * 2 + hf;
                const int rowg = qbase + wm + mi * 16 + hf * 8 + g;
                float vv[8];
                float lm = run_m[s];
                #pragma unroll
                for (int ni = 0; ni < 4; ni++) {
                    #pragma unroll
                    for (int q = 0; q < 2; q++) {
                        float sv = sacc[mi][ni][hf * 2 + q] * scale;
                        if (msk && (kbase + wx * 32 + ni * 8 + 2 * tg + q > rowg)) sv = -1e30f;
                        vv[ni * 2 + q] = sv;
                        lm = fmaxf(lm, sv);
                    }
                }
                float al = 0.0f;
                #pragma unroll
                for (int idx = 0; idx < 8; idx++) al += __expf(vv[idx] - lm);
                run_l[s] = run_l[s] * __expf(run_m[s] - lm) + al;
                run_m[s] = lm;
            }
        }
    }

    #pragma unroll
    for (int s = 0; s < 4; s++) {
        float m = run_m[s], l = run_l[s];
        #pragma unroll
        for (int mk = 1; mk < 4; mk <<= 1) {
            float om = __shfl_xor_sync(0xffffffffu, m, mk);
            float ol = __shfl_xor_sync(0xffffffffu, l, mk);
            float mn = fmaxf(m, om);
            l = l * __expf(m - mn) + ol * __expf(om - mn);
            m = mn;
        }
        run_m[s] = m; run_l[s] = l;
    }
    if (tg == 0) {
        #pragma unroll
        for (int s = 0; s < 4; s++) {
            int row = wm + (s >> 1) * 16 + (s & 1) * 8 + g;
            smP[row * 4 + wx * 2]     = run_m[s];
            smP[row * 4 + wx * 2 + 1] = run_l[s];
        }
    }
    __syncthreads();
    if (tid < 128) {
        float m0 = smP[tid * 4], l0 = smP[tid * 4 + 1];
        float m1 = smP[tid * 4 + 2], l1 = smP[tid * 4 + 3];
        float mn = fmaxf(m0, m1);
        float l = l0 * __expf(m0 - mn) + l1 * __expf(m1 - mn);
        sm_m[tid] = mn;
        sm_il[tid] = 1.0f / l;
    }
    __syncthreads();

    float m_s[4], il_s[4];
    #pragma unroll
    for (int s = 0; s < 4; s++) {
        int row = wm + (s >> 1) * 16 + (s & 1) * 8 + g;
        m_s[s] = sm_m[row];
        il_s[s] = sm_il[row];
    }

    float oacc[2][4][4];
    #pragma unroll
    for (int mi = 0; mi < 2; mi++)
        #pragma unroll
        for (int ni = 0; ni < 4; ni++)
            #pragma unroll
            for (int q = 0; q < 4; q++) oacc[mi][ni][q] = 0.0f;

    // ---------------- phase 2: P write + P@V ----------------
    for (int jt = 0; jt <= jmax; jt++) {
        const int kbase = jt * 64;
        __syncthreads();
        const float* kg = kp + ((size_t)(b * Sz + kbase)) * Dz + h * 64;
        const float* vg = vp + ((size_t)(b * Sz + kbase)) * Dz + h * 64;
        #pragma unroll
        for (int u = 0; u < 4; u++) {
            int f = tid + u * 256;
            int r = f >> 4, c4 = (f & 15) * 4;
            *(float4*)&Ks[r * 68 + c4] = *(const float4*)&kg[(size_t)r * Dz + c4];
            *(float4*)&Vs[r * 68 + c4] = *(const float4*)&vg[(size_t)r * Dz + c4];
        }
        __syncthreads();

        float sacc[2][4][4];
        #pragma unroll
        for (int mi = 0; mi < 2; mi++)
            #pragma unroll
            for (int ni = 0; ni < 4; ni++)
                #pragma unroll
                for (int q = 0; q < 4; q++) sacc[mi][ni][q] = 0.0f;

        #pragma unroll
        for (int k8 = 0; k8 < 64; k8 += 8) {
            uint32_t af[2][4];
            #pragma unroll
            for (int mi = 0; mi < 2; mi++) {
                const int r0 = (wm + mi * 16 + g) * 68 + k8 + tg;
                af[mi][0] = __float_as_uint(Qs[r0]);
                af[mi][1] = __float_as_uint(Qs[r0 + 8 * 68]);
                af[mi][2] = __float_as_uint(Qs[r0 + 4]);
                af[mi][3] = __float_as_uint(Qs[r0 + 8 * 68 + 4]);
            }
            #pragma unroll
            for (int ni = 0; ni < 4; ni++) {
                const int cb = (wx * 32 + ni * 8 + g) * 68 + k8 + tg;
                uint32_t b0 = __float_as_uint(Ks[cb]);
                uint32_t b1 = __float_as_uint(Ks[cb + 4]);
                mma8(sacc[0][ni], af[0], b0, b1);
                mma8(sacc[1][ni], af[1], b0, b1);
            }
        }

        const bool msk = (jt >= 2 * qt);
        #pragma unroll
        for (int mi = 0; mi < 2; mi++) {
            #pragma unroll
            for (int hf = 0; hf < 2; hf++) {
                const int s = mi * 2 + hf;
                const int rowl = wm + mi * 16 + hf * 8 + g;
                const int rowg = qbase + rowl;
                const float mm = m_s[s], il = il_s[s];
                #pragma unroll
                for (int ni = 0; ni < 4; ni++) {
                    const int col0 = kbase + wx * 32 + ni * 8 + 2 * tg;
                    float sv0 = sacc[mi][ni][hf * 2] * scale;
                    float sv1 = sacc[mi][ni][hf * 2 + 1] * scale;
                    float p0 = (msk && (col0 > rowg)) ? 0.0f : __expf(sv0 - mm) * il;
                    float p1 = (msk && (col0 + 1 > rowg)) ? 0.0f : __expf(sv1 - mm) * il;
                    float2 w; w.x = p0; w.y = p1;
                    *(float2*)&Ps[rowl * 68 + wx * 32 + ni * 8 + 2 * tg] = w;
                }
            }
        }
        __syncthreads();

        #pragma unroll
        for (int k8 = 0; k8 < 64; k8 += 8) {
            uint32_t pa[2][4];
            #pragma unroll
            for (int mi = 0; mi < 2; mi++) {
                const int r0 = (wm + mi * 16 + g) * 68 + k8 + tg;
                pa[mi][0] = __float_as_uint(tf32r(Ps[r0]));
                pa[mi][1] = __float_as_uint(tf32r(Ps[r0 + 8 * 68]));
                pa[mi][2] = __float_as_uint(tf32r(Ps[r0 + 4]));
                pa[mi][3] = __float_as_uint(tf32r(Ps[r0 + 8 * 68 + 4]));
            }
            #pragma unroll
            for (int ni = 0; ni < 4; ni++) {
                const int c0 = wx * 32 + ni * 8 + g;
                uint32_t b0 = __float_as_uint(Vs[(k8 + tg) * 68 + c0]);
                uint32_t b1 = __float_as_uint(Vs[(k8 + 4 + tg) * 68 + c0]);
                mma8(oacc[0][ni], pa[0], b0, b1);
                mma8(oacc[1][ni], pa[1], b0, b1);
            }
        }

        #pragma unroll
        for (int u = 0; u < 8; u++) {
            int f = tid + u * 256;
            int r = f >> 4, c4 = (f & 15) * 4;
            *(float4*)&ab[(size_t)(qbase + r) * Sz + kbase + c4] = *(float4*)&Ps[r * 68 + c4];
        }
    }

    // write v_att rounded (feeds Wo GEMM which expects tf32 inputs)
    #pragma unroll
    for (int mi = 0; mi < 2; mi++) {
        const int r0 = qbase + wm + mi * 16 + g;
        #pragma unroll
        for (int ni = 0; ni < 4; ni++) {
            const int c = h * 64 + wx * 32 + ni * 8 + 2 * tg;
            float2 w0; w0.x = tf32r(oacc[mi][ni][0]); w0.y = tf32r(oacc[mi][ni][1]);
            float2 w1; w1.x = tf32r(oacc[mi][ni][2]); w1.y = tf32r(oacc[mi][ni][3]);
            *(float2*)&vatt[((size_t)(b * Sz + r0)) * Dz + c] = w0;
            *(float2*)&vatt[((size_t)(b * Sz + r0 + 8)) * Dz + c] = w1;
        }
    }
}

// ---------------- fused residual add + LayerNorm (single pass, shfl reduce) ----------------
__global__ __launch_bounds__(256)
void ln_add(const float* __restrict__ x, const float* __restrict__ y,
            const float* __restrict__ g, const float* __restrict__ bt,
            float* __restrict__ out, float* __restrict__ out_r)
{
    __shared__ float wsum[8], wsq[8];
    const int r = blockIdx.x, tid = threadIdx.x;
    const int lane = tid & 31, warp = tid >> 5;

    float4 x4 = *(const float4*)&x[(size_t)r * Dz + tid * 4];
    float4 y4 = *(const float4*)&y[(size_t)r * Dz + tid * 4];
    float t0 = x4.x + y4.x, t1 = x4.y + y4.y, t2 = x4.z + y4.z, t3 = x4.w + y4.w;

    float s = t0 + t1 + t2 + t3;
    float q = t0 * t0 + t1 * t1 + t2 * t2 + t3 * t3;
    #pragma unroll
    for (int m = 16; m > 0; m >>= 1) {
        s += __shfl_xor_sync(0xffffffffu, s, m);
        q += __shfl_xor_sync(0xffffffffu, q, m);
    }
    if (lane == 0) { wsum[warp] = s; wsq[warp] = q; }
    __syncthreads();
    if (tid < 32) {
        float s8 = (lane < 8) ? wsum[lane] : 0.0f;
        float q8 = (lane < 8) ? wsq[lane] : 0.0f;
        #pragma unroll
        for (int m = 4; m > 0; m >>= 1) {
            s8 += __shfl_xor_sync(0xffffffffu, s8, m);
            q8 += __shfl_xor_sync(0xffffffffu, q8, m);
        }
        if (lane == 0) { wsum[0] = s8; wsq[0] = q8; }
    }
    __syncthreads();

    const float mu = wsum[0] * (1.0f / Dz);
    const float var = wsq[0] * (1.0f / Dz) - mu * mu;
    const float rstd = rsqrtf(var + 1e-5f);

    float4 g4 = *(const float4*)&g[tid * 4];
    float4 b4 = *(const float4*)&bt[tid * 4];
    float4 o;
    o.x = g4.x * (t0 - mu) * rstd + b4.x;
    o.y = g4.y * (t1 - mu) * rstd + b4.y;
    o.z = g4.z * (t2 - mu) * rstd + b4.z;
    o.w = g4.w * (t3 - mu) * rstd + b4.w;
    *(float4*)&out[(size_t)r * Dz + tid * 4] = o;
    if (out_r) {
        float4 orr;
        orr.x = tf32r(o.x); orr.y = tf32r(o.y); orr.z = tf32r(o.z); orr.w = tf32r(o.w);
        *(float4*)&out_r[(size_t)r * Dz + tid * 4] = orr;
    }
}

// ---------------- host launcher ----------------
extern "C" void kernel_launch(void* const* d_in, const int* in_sizes, int n_in,
                              void* d_out, int out_size)
{
    const float* Q   = (const float*)d_in[0];
    const float* Kin = (const float*)d_in[1];
    const float* Vin = (const float*)d_in[2];
    const float* W_q = (const float*)d_in[4];
    const float* W_k = (const float*)d_in[5];
    const float* W_v = (const float*)d_in[6];
    const float* W_o = (const float*)d_in[7];
    const float* w1  = (const float*)d_in[8];
    const float* b1  = (const float*)d_in[9];
    const float* w2  = (const float*)d_in[10];
    const float* b2  = (const float*)d_in[11];
    const float* lng = (const float*)d_in[12];
    const float* lnb = (const float*)d_in[13];

    float *qp, *kp, *vp, *vattp, *Xp, *Xr, *Qr, *h1p, *tp, *wr, *attfb;
    cudaGetSymbolAddress((void**)&qp, g_q);
    cudaGetSymbolAddress((void**)&kp, g_k);
    cudaGetSymbolAddress((void**)&vp, g_v);
    cudaGetSymbolAddress((void**)&vattp, g_vatt);
    cudaGetSymbolAddress((void**)&Xp, g_X);
    cudaGetSymbolAddress((void**)&Xr, g_xr);
    cudaGetSymbolAddress((void**)&Qr, g_qr);
    cudaGetSymbolAddress((void**)&h1p, g_h1);
    cudaGetSymbolAddress((void**)&tp, g_t);
    cudaGetSymbolAddress((void**)&wr, g_wr);
    cudaGetSymbolAddress((void**)&attfb, g_attfb);

    float* wq_r = wr;
    float* wk_r = wr + 1 * (size_t)Dz * Dz;
    float* wv_r = wr + 2 * (size_t)Dz * Dz;
    float* wo_r = wr + 3 * (size_t)Dz * Dz;
    float* w1_r = wr + 4 * (size_t)Dz * Dz;
    float* w2_r = wr + 5 * (size_t)Dz * Dz;
    float* Kr = h1p;   // temp rounded K input (g_h1 free until FFN)
    float* Vr = tp;    // temp rounded V input (g_t free until Wo GEMM)

    const int SM_NN = 2 * (ASTG + 4352) * 4;   // 71680
    const int SM_NT = 2 * (ASTG + 4608) * 4;   // 73728
    cudaFuncSetAttribute(attn_fused, cudaFuncAttributeMaxDynamicSharedMemorySize, AT_SMEM);
    cudaFuncSetAttribute(qkv_gemm, cudaFuncAttributeMaxDynamicSharedMemorySize, SM_NN);
    cudaFuncSetAttribute(tgemm2<false,0,false>, cudaFuncAttributeMaxDynamicSharedMemorySize, SM_NN);
    cudaFuncSetAttribute(tgemm2<true,1,true>,   cudaFuncAttributeMaxDynamicSharedMemorySize, SM_NT);
    cudaFuncSetAttribute(tgemm2<true,2,false>,  cudaFuncAttributeMaxDynamicSharedMemorySize, SM_NT);

    const size_t OUT_MAIN = (size_t)Mz * Dz;            // 8388608
    const size_t ATT_N    = (size_t)BHz * Sz * Sz;      // 134217728
    float* outp = (float*)d_out;
    float* att  = ((size_t)out_size >= OUT_MAIN + ATT_N) ? (outp + OUT_MAIN) : attfb;

    dim3 gg(Dz / 128, Mz / 128);
    dim3 gq(Dz / 128, Mz / 128, 3);
    dim3 gb(256);
    dim3 ag(BHz, 8);
    const int M4 = (Mz * Dz) / 4, W4 = (Dz * Dz) / 4;

    // pre-round activations + weights once (semantically identical to per-tile cvt)
    roundcopy3<<<dim3(M4 / 256, 3), 256>>>(
        (const float4*)Q, (const float4*)Kin, (const float4*)Vin,
        (float4*)Qr, (float4*)Kr, (float4*)Vr);
    roundcopy6<<<dim3(W4 / 256, 6), 256>>>(
        (const float4*)W_q, (const float4*)W_k, (const float4*)W_v,
        (const float4*)W_o, (const float4*)w1, (const float4*)w2,
        (float4*)wr, W4);   // seg in float4 units

    // merged QKV projections (rounded outputs feed attention)
    qkv_gemm<<<gq, gb, SM_NN>>>(Qr, Kr, Vr, wq_r, wk_r, wv_r, qp, kp, vp, Mz, Dz, Dz);
    // fused flash attention (vatt rounded in epilogue)
    attn_fused<<<ag, gb, AT_SMEM>>>(qp, kp, vp, att, vattp);
    // output projection + first residual LN (residual uses ORIGINAL Q)
    tgemm2<false,0,false><<<gg, gb, SM_NN>>>(vattp, wo_r, nullptr, tp, Mz, Dz, Dz);
    ln_add<<<Mz, 256>>>(Q, tp, lng, lnb, Xp, Xr);
    // FFN
    tgemm2<true,1,true><<<gg, gb, SM_NT>>>(Xr, w1_r, b1, h1p, Mz, Dz, Dz);
    tgemm2<true,2,false><<<gg, gb, SM_NT>>>(h1p, w2_r, b2, tp, Mz, Dz, Dz);
    // final residual LN -> d_out
    ln_add<<<Mz, 256>>>(Xp, tp, lng, lnb, outp, nullptr);
}

// round 12
// speedup vs baseline: 1.4669x; 1.4669x over previous
#include <cuda_runtime.h>
#include <math.h>
#include <stdint.h>

// Problem constants
#define Bz 8
#define Sz 1024
#define Dz 1024
#define Hz 16
#define Mz (Bz*Sz)          // 8192 rows
#define BHz (Bz*Hz)         // 128 (b,h) pairs

// ---------------- scratch (device globals: no allocation allowed) ----------------
__device__ float g_q[Mz*Dz];
__device__ float g_k[Mz*Dz];
__device__ float g_v[Mz*Dz];
__device__ float g_vatt[Mz*Dz];
__device__ float g_X[Mz*Dz];
__device__ float g_xr[Mz*Dz];
__device__ float g_qr[Mz*Dz];
__device__ float g_h1[Mz*Dz];       // FFN hidden; also temp rounded-K before attention
__device__ float g_t[Mz*Dz];        // GEMM temp; also temp rounded-V before attention
__device__ float g_wr[6*Dz*Dz];     // pre-rounded weights: Wq Wk Wv Wo w1 w2
__device__ float g_attfb[134217728];

__device__ __forceinline__ float gelu_exact(float x) {
    return 0.5f * x * (1.0f + erff(x * 0.70710678118654752f));
}

__device__ __forceinline__ float tf32r(float x) {
    uint32_t u;
    asm("cvt.rna.tf32.f32 %0, %1;" : "=r"(u) : "f"(x));
    return __uint_as_float(u);
}

__device__ __forceinline__ void mma8(float* c, const uint32_t* a, uint32_t b0, uint32_t b1) {
    asm("mma.sync.aligned.m16n8k8.row.col.f32.tf32.tf32.f32 "
        "{%0,%1,%2,%3}, {%4,%5,%6,%7}, {%8,%9}, {%0,%1,%2,%3};"
        : "+f"(c[0]), "+f"(c[1]), "+f"(c[2]), "+f"(c[3])
        : "r"(a[0]), "r"(a[1]), "r"(a[2]), "r"(a[3]), "r"(b0), "r"(b1));
}

__device__ __forceinline__ void cpa16(uint32_t s, const void* g) {
    asm volatile("cp.async.ca.shared.global [%0], [%1], 16;\n" :: "r"(s), "l"(g));
}

// ---------------- batched tf32 round-copy (grid.y = segment) ----------------
__global__ void roundcopy3(const float4* __restrict__ s0, const float4* __restrict__ s1,
                           const float4* __restrict__ s2,
                           float4* __restrict__ d0, float4* __restrict__ d1,
                           float4* __restrict__ d2)
{
    int i = blockIdx.x * blockDim.x + threadIdx.x;
    const float4* s = (blockIdx.y == 0) ? s0 : (blockIdx.y == 1) ? s1 : s2;
    float4* d = (blockIdx.y == 0) ? d0 : (blockIdx.y == 1) ? d1 : d2;
    float4 v = s[i];
    float4 t;
    t.x = tf32r(v.x); t.y = tf32r(v.y); t.z = tf32r(v.z); t.w = tf32r(v.w);
    d[i] = t;
}

// seg is the per-matrix stride IN FLOAT4 UNITS (Dz*Dz/4).
__global__ void roundcopy6(const float4* __restrict__ s0, const float4* __restrict__ s1,
                           const float4* __restrict__ s2, const float4* __restrict__ s3,
                           const float4* __restrict__ s4, const float4* __restrict__ s5,
                           float4* __restrict__ dst, int seg)
{
    int i = blockIdx.x * blockDim.x + threadIdx.x;
    const float4* s;
    switch (blockIdx.y) {
        case 0: s = s0; break; case 1: s = s1; break; case 2: s = s2; break;
        case 3: s = s3; break; case 4: s = s4; break; default: s = s5; break;
    }
    float4 v = s[i];
    float4 t;
    t.x = tf32r(v.x); t.y = tf32r(v.y); t.z = tf32r(v.z); t.w = tf32r(v.w);
    dst[(size_t)blockIdx.y * seg + i] = t;
}

// ---------------- tf32 tensor-core GEMM (cp.async 2-stage, k32) ----------------
// ROUND-7 PROVEN CORE (115us/GEMM measured). Inputs pre-rounded to tf32.
// A: [M,K] row-major. TB=false: B [K,N] (NN). TB=true: B [N,K] (NT, C = A@B^T).
// 128x128x32 tiles, 256 threads (8 warps 2x4), warp tile 64x32 via m16n8k8.
#define ASTG 4608            // 128*36 floats per stage
template<bool TB, int EPI, bool RND>   // EPI: 0 none, 1 bias+gelu, 2 bias
__global__ __launch_bounds__(256, 2)
void tgemm2(const float* __restrict__ A, const float* __restrict__ Bm,
            const float* __restrict__ bias, float* __restrict__ C,
            int M, int N, int K)
{
    constexpr int BSTG = TB ? 4608 : 4352;   // [n][k]s36 : [k][n]s136
    extern __shared__ float sh[];
    float* As = sh;
    float* Bs = sh + 2 * ASTG;

    const int tid = threadIdx.x;
    const int lane = tid & 31, warp = tid >> 5;
    const int wm = (warp >> 2) * 64, wn = (warp & 3) * 32;
    const int g = lane >> 2, tg = lane & 3;
    const int bx = blockIdx.x * 128, by = blockIdx.y * 128;

    const uint32_t sa = (uint32_t)__cvta_generic_to_shared(As);
    const uint32_t sb = (uint32_t)__cvta_generic_to_shared(Bs);

    float acc[4][4][4];
    #pragma unroll
    for (int mi = 0; mi < 4; mi++)
        #pragma unroll
        for (int ni = 0; ni < 4; ni++)
            #pragma unroll
            for (int q = 0; q < 4; q++) acc[mi][ni][q] = 0.0f;

    int ar[4], ac[4], br[4], bc[4];
    #pragma unroll
    for (int u = 0; u < 4; u++) {
        int f = tid + u * 256;
        ar[u] = f >> 3; ac[u] = (f & 7) * 4;               // A: 128 rows x 8 chunks
        if (TB) { br[u] = f >> 3; bc[u] = (f & 7) * 4; }   // B: 128 rows x 8 chunks
        else    { br[u] = f >> 5; bc[u] = (f & 31) * 4; }  // B: 32 rows x 32 chunks
    }

    const int nk = K >> 5;

    // prologue: stage 0
    {
        #pragma unroll
        for (int u = 0; u < 4; u++)
            cpa16(sa + (uint32_t)(ar[u] * 36 + ac[u]) * 4,
                  &A[(size_t)(by + ar[u]) * K + ac[u]]);
        if (TB) {
            #pragma unroll
            for (int u = 0; u < 4; u++)
                cpa16(sb + (uint32_t)(br[u] * 36 + bc[u]) * 4,
                      &Bm[(size_t)(bx + br[u]) * K + bc[u]]);
        } else {
            #pragma unroll
            for (int u = 0; u < 4; u++)
                cpa16(sb + (uint32_t)(br[u] * 136 + bc[u]) * 4,
                      &Bm[(size_t)(br[u]) * N + bx + bc[u]]);
        }
        asm volatile("cp.async.commit_group;\n" ::);
    }

    for (int kt = 0; kt < nk; kt++) {
        const int p = kt & 1;
        if (kt + 1 < nk) {
            const int ko = (kt + 1) * 32;
            const uint32_t pa = sa + (uint32_t)(((kt + 1) & 1) * ASTG) * 4;
            const uint32_t pb = sb + (uint32_t)(((kt + 1) & 1) * BSTG) * 4;
            #pragma unroll
            for (int u = 0; u < 4; u++)
                cpa16(pa + (uint32_t)(ar[u] * 36 + ac[u]) * 4,
                      &A[(size_t)(by + ar[u]) * K + ko + ac[u]]);
            if (TB) {
                #pragma unroll
                for (int u = 0; u < 4; u++)
                    cpa16(pb + (uint32_t)(br[u] * 36 + bc[u]) * 4,
                          &Bm[(size_t)(bx + br[u]) * K + ko + bc[u]]);
            } else {
                #pragma unroll
                for (int u = 0; u < 4; u++)
                    cpa16(pb + (uint32_t)(br[u] * 136 + bc[u]) * 4,
                          &Bm[(size_t)(ko + br[u]) * N + bx + bc[u]]);
            }
            asm volatile("cp.async.commit_group;\n" ::);
            asm volatile("cp.async.wait_group 1;\n" ::);
        } else {
            asm volatile("cp.async.wait_group 0;\n" ::);
        }
        __syncthreads();

        const float* Ap = As + p * ASTG;
        const float* Bp = Bs + p * BSTG;
        #pragma unroll
        for (int k8 = 0; k8 < 32; k8 += 8) {
            uint32_t af[4][4];
            #pragma unroll
            for (int mi = 0; mi < 4; mi++) {
                const int r0 = (wm + mi * 16 + g) * 36 + k8 + tg;
                af[mi][0] = __float_as_uint(Ap[r0]);
                af[mi][1] = __float_as_uint(Ap[r0 + 8 * 36]);
                af[mi][2] = __float_as_uint(Ap[r0 + 4]);
                af[mi][3] = __float_as_uint(Ap[r0 + 8 * 36 + 4]);
            }
            #pragma unroll
            for (int ni = 0; ni < 4; ni++) {
                const int c0 = wn + ni * 8 + g;
                uint32_t b0, b1;
                if (TB) {
                    b0 = __float_as_uint(Bp[c0 * 36 + k8 + tg]);
                    b1 = __float_as_uint(Bp[c0 * 36 + k8 + 4 + tg]);
                } else {
                    b0 = __float_as_uint(Bp[(k8 + tg) * 136 + c0]);
                    b1 = __float_as_uint(Bp[(k8 + 4 + tg) * 136 + c0]);
                }
                #pragma unroll
                for (int mi = 0; mi < 4; mi++) mma8(acc[mi][ni], af[mi], b0, b1);
            }
        }
        __syncthreads();
    }

    #pragma unroll
    for (int mi = 0; mi < 4; mi++) {
        const int r0 = by + wm + mi * 16 + g;
        #pragma unroll
        for (int ni = 0; ni < 4; ni++) {
            const int c0 = bx + wn + ni * 8 + 2 * tg;
            float v0 = acc[mi][ni][0], v1 = acc[mi][ni][1];
            float v2 = acc[mi][ni][2], v3 = acc[mi][ni][3];
            if (EPI != 0) {
                float bb0 = bias[c0], bb1 = bias[c0 + 1];
                v0 += bb0; v1 += bb1; v2 += bb0; v3 += bb1;
            }
            if (EPI == 1) {
                v0 = gelu_exact(v0); v1 = gelu_exact(v1);
                v2 = gelu_exact(v2); v3 = gelu_exact(v3);
            }
            if (RND) {
                v0 = tf32r(v0); v1 = tf32r(v1); v2 = tf32r(v2); v3 = tf32r(v3);
            }
            float2 w0; w0.x = v0; w0.y = v1;
            float2 w1; w1.x = v2; w1.y = v3;
            *(float2*)&C[(size_t)r0 * N + c0] = w0;
            *(float2*)&C[(size_t)(r0 + 8) * N + c0] = w1;
        }
    }
}

// ---------------- fused tensor-core flash attention (unchanged, known good) ----------------
#define AT_SMEM 107520
__global__ __launch_bounds__(256, 2)
void attn_fused(const float* __restrict__ qp, const float* __restrict__ kp,
                const float* __restrict__ vp, float* __restrict__ att,
                float* __restrict__ vatt)
{
    extern __shared__ float sh[];
    float* Qs   = sh;                    // [128][68]
    float* Ks   = sh + 128 * 68;         // [64][68]
    float* Vs   = Ks + 64 * 68;          // [64][68]
    float* Ps   = Vs + 64 * 68;          // [128][68]
    float* smP  = Ps + 128 * 68;         // [128][4]
    float* sm_m = smP + 512;             // [128]
    float* sm_il= sm_m + 128;            // [128]

    const int bh = blockIdx.x, b = bh >> 4, h = bh & 15;
    const int qt = 7 - blockIdx.y;
    const int qbase = qt * 128;
    const int tid = threadIdx.x;
    const int lane = tid & 31, warp = tid >> 5;
    const int wy = warp >> 1, wx = warp & 1;
    const int wm = wy * 32;
    const int g = lane >> 2, tg = lane & 3;
    const float scale = 1.0f / (8.0f + 1e-6f);

    const float* qg = qp + ((size_t)(b * Sz + qbase)) * Dz + h * 64;
    #pragma unroll
    for (int u = 0; u < 8; u++) {
        int f = tid + u * 256;
        int r = f >> 4, c4 = (f & 15) * 4;
        *(float4*)&Qs[r * 68 + c4] = *(const float4*)&qg[(size_t)r * Dz + c4];
    }

    float* ab = att + (size_t)bh * Sz * Sz;
    {
        float4 z; z.x = z.y = z.z = z.w = 0.0f;
        for (int j2 = 2 * qt + 2; j2 < 16; j2++) {
            const int kb = j2 * 64;
            #pragma unroll
            for (int u = 0; u < 8; u++) {
                int f = tid + u * 256;
                int r = f >> 4, c4 = (f & 15) * 4;
                *(float4*)&ab[(size_t)(qbase + r) * Sz + kb + c4] = z;
            }
        }
    }

    const int jmax = 2 * qt + 1;
    float run_m[4], run_l[4];
    #pragma unroll
    for (int s = 0; s < 4; s++) { run_m[s] = -1e30f; run_l[s] = 0.0f; }

    // ---------------- phase 1: softmax stats ----------------
    for (int jt = 0; jt <= jmax; jt++) {
        const int kbase = jt * 64;
        __syncthreads();
        const float* kg = kp + ((size_t)(b * Sz + kbase)) * Dz + h * 64;
        #pragma unroll
        for (int u = 0; u < 4; u++) {
            int f = tid + u * 256;
            int r = f >> 4, c4 = (f & 15) * 4;
            *(float4*)&Ks[r * 68 + c4] = *(const float4*)&kg[(size_t)r * Dz + c4];
        }
        __syncthreads();

        float sacc[2][4][4];
        #pragma unroll
        for (int mi = 0; mi < 2; mi++)
            #pragma unroll
            for (int ni = 0; ni < 4; ni++)
                #pragma unroll
                for (int q = 0; q < 4; q++) sacc[mi][ni][q] = 0.0f;

        #pragma unroll
        for (int k8 = 0; k8 < 64; k8 += 8) {
            uint32_t af[2][4];
            #pragma unroll
            for (int mi = 0; mi < 2; mi++) {
                const int r0 = (wm + mi * 16 + g) * 68 + k8 + tg;
                af[mi][0] = __float_as_uint(Qs[r0]);
                af[mi][1] = __float_as_uint(Qs[r0 + 8 * 68]);
                af[mi][2] = __float_as_uint(Qs[r0 + 4]);
                af[mi][3] = __float_as_uint(Qs[r0 + 8 * 68 + 4]);
            }
            #pragma unroll
            for (int ni = 0; ni < 4; ni++) {
                const int cb = (wx * 32 + ni * 8 + g) * 68 + k8 + tg;
                uint32_t b0 = __float_as_uint(Ks[cb]);
                uint32_t b1 = __float_as_uint(Ks[cb + 4]);
                mma8(sacc[0][ni], af[0], b0, b1);
                mma8(sacc[1][ni], af[1], b0, b1);
            }
        }

        const bool msk = (jt >= 2 * qt);
        #pragma unroll
        for (int mi = 0; mi < 2; mi++) {
            #pragma unroll
            for (int hf = 0; hf < 2; hf++) {
                const int s = mi * 2 + hf;
                const int rowg = qbase + wm + mi * 16 + hf * 8 + g;
                float vv[8];
                float lm = run_m[s];
                #pragma unroll
                for (int ni = 0; ni < 4; ni++) {
                    #pragma unroll
                    for (int q = 0; q < 2; q++) {
                        float sv = sacc[mi][ni][hf * 2 + q] * scale;
                        if (msk && (kbase + wx * 32 + ni * 8 + 2 * tg + q > rowg)) sv = -1e30f;
                        vv[ni * 2 + q] = sv;
                        lm = fmaxf(lm, sv);
                    }
                }
                float al = 0.0f;
                #pragma unroll
                for (int idx = 0; idx < 8; idx++) al += __expf(vv[idx] - lm);
                run_l[s] = run_l[s] * __expf(run_m[s] - lm) + al;
                run_m[s] = lm;
            }
        }
    }

    #pragma unroll
    for (int s = 0; s < 4; s++) {
        float m = run_m[s], l = run_l[s];
        #pragma unroll
        for (int mk = 1; mk < 4; mk <<= 1) {
            float om = __shfl_xor_sync(0xffffffffu, m, mk);
            float ol = __shfl_xor_sync(0xffffffffu, l, mk);
            float mn = fmaxf(m, om);
            l = l * __expf(m - mn) + ol * __expf(om - mn);
            m = mn;
        }
        run_m[s] = m; run_l[s] = l;
    }
    if (tg == 0) {
        #pragma unroll
        for (int s = 0; s < 4; s++) {
            int row = wm + (s >> 1) * 16 + (s & 1) * 8 + g;
            smP[row * 4 + wx * 2]     = run_m[s];
            smP[row * 4 + wx * 2 + 1] = run_l[s];
        }
    }
    __syncthreads();
    if (tid < 128) {
        float m0 = smP[tid * 4], l0 = smP[tid * 4 + 1];
        float m1 = smP[tid * 4 + 2], l1 = smP[tid * 4 + 3];
        float mn = fmaxf(m0, m1);
        float l = l0 * __expf(m0 - mn) + l1 * __expf(m1 - mn);
        sm_m[tid] = mn;
        sm_il[tid] = 1.0f / l;
    }
    __syncthreads();

    float m_s[4], il_s[4];
    #pragma unroll
    for (int s = 0; s < 4; s++) {
        int row = wm + (s >> 1) * 16 + (s & 1) * 8 + g;
        m_s[s] = sm_m[row];
        il_s[s] = sm_il[row];
    }

    float oacc[2][4][4];
    #pragma unroll
    for (int mi = 0; mi < 2; mi++)
        #pragma unroll
        for (int ni = 0; ni < 4; ni++)
            #pragma unroll
            for (int q = 0; q < 4; q++) oacc[mi][ni][q] = 0.0f;

    // ---------------- phase 2: P write + P@V ----------------
    for (int jt = 0; jt <= jmax; jt++) {
        const int kbase = jt * 64;
        __syncthreads();
        const float* kg = kp + ((size_t)(b * Sz + kbase)) * Dz + h * 64;
        const float* vg = vp + ((size_t)(b * Sz + kbase)) * Dz + h * 64;
        #pragma unroll
        for (int u = 0; u < 4; u++) {
            int f = tid + u * 256;
            int r = f >> 4, c4 = (f & 15) * 4;
            *(float4*)&Ks[r * 68 + c4] = *(const float4*)&kg[(size_t)r * Dz + c4];
            *(float4*)&Vs[r * 68 + c4] = *(const float4*)&vg[(size_t)r * Dz + c4];
        }
        __syncthreads();

        float sacc[2][4][4];
        #pragma unroll
        for (int mi = 0; mi < 2; mi++)
            #pragma unroll
            for (int ni = 0; ni < 4; ni++)
                #pragma unroll
                for (int q = 0; q < 4; q++) sacc[mi][ni][q] = 0.0f;

        #pragma unroll
        for (int k8 = 0; k8 < 64; k8 += 8) {
            uint32_t af[2][4];
            #pragma unroll
            for (int mi = 0; mi < 2; mi++) {
                const int r0 = (wm + mi * 16 + g) * 68 + k8 + tg;
                af[mi][0] = __float_as_uint(Qs[r0]);
                af[mi][1] = __float_as_uint(Qs[r0 + 8 * 68]);
                af[mi][2] = __float_as_uint(Qs[r0 + 4]);
                af[mi][3] = __float_as_uint(Qs[r0 + 8 * 68 + 4]);
            }
            #pragma unroll
            for (int ni = 0; ni < 4; ni++) {
                const int cb = (wx * 32 + ni * 8 + g) * 68 + k8 + tg;
                uint32_t b0 = __float_as_uint(Ks[cb]);
                uint32_t b1 = __float_as_uint(Ks[cb + 4]);
                mma8(sacc[0][ni], af[0], b0, b1);
                mma8(sacc[1][ni], af[1], b0, b1);
            }
        }

        const bool msk = (jt >= 2 * qt);
        #pragma unroll
        for (int mi = 0; mi < 2; mi++) {
            #pragma unroll
            for (int hf = 0; hf < 2; hf++) {
                const int s = mi * 2 + hf;
                const int rowl = wm + mi * 16 + hf * 8 + g;
                const int rowg = qbase + rowl;
                const float mm = m_s[s], il = il_s[s];
                #pragma unroll
                for (int ni = 0; ni < 4; ni++) {
                    const int col0 = kbase + wx * 32 + ni * 8 + 2 * tg;
                    float sv0 = sacc[mi][ni][hf * 2] * scale;
                    float sv1 = sacc[mi][ni][hf * 2 + 1] * scale;
                    float p0 = (msk && (col0 > rowg)) ? 0.0f : __expf(sv0 - mm) * il;
                    float p1 = (msk && (col0 + 1 > rowg)) ? 0.0f : __expf(sv1 - mm) * il;
                    float2 w; w.x = p0; w.y = p1;
                    *(float2*)&Ps[rowl * 68 + wx * 32 + ni * 8 + 2 * tg] = w;
                }
            }
        }
        __syncthreads();

        #pragma unroll
        for (int k8 = 0; k8 < 64; k8 += 8) {
            uint32_t pa[2][4];
            #pragma unroll
            for (int mi = 0; mi < 2; mi++) {
                const int r0 = (wm + mi * 16 + g) * 68 + k8 + tg;
                pa[mi][0] = __float_as_uint(tf32r(Ps[r0]));
                pa[mi][1] = __float_as_uint(tf32r(Ps[r0 + 8 * 68]));
                pa[mi][2] = __float_as_uint(tf32r(Ps[r0 + 4]));
                pa[mi][3] = __float_as_uint(tf32r(Ps[r0 + 8 * 68 + 4]));
            }
            #pragma unroll
            for (int ni = 0; ni < 4; ni++) {
                const int c0 = wx * 32 + ni * 8 + g;
                uint32_t b0 = __float_as_uint(Vs[(k8 + tg) * 68 + c0]);
                uint32_t b1 = __float_as_uint(Vs[(k8 + 4 + tg) * 68 + c0]);
                mma8(oacc[0][ni], pa[0], b0, b1);
                mma8(oacc[1][ni], pa[1], b0, b1);
            }
        }

        #pragma unroll
        for (int u = 0; u < 8; u++) {
            int f = tid + u * 256;
            int r = f >> 4, c4 = (f & 15) * 4;
            *(float4*)&ab[(size_t)(qbase + r) * Sz + kbase + c4] = *(float4*)&Ps[r * 68 + c4];
        }
    }

    // write v_att rounded (feeds Wo GEMM which expects tf32 inputs)
    #pragma unroll
    for (int mi = 0; mi < 2; mi++) {
        const int r0 = qbase + wm + mi * 16 + g;
        #pragma unroll
        for (int ni = 0; ni < 4; ni++) {
            const int c = h * 64 + wx * 32 + ni * 8 + 2 * tg;
            float2 w0; w0.x = tf32r(oacc[mi][ni][0]); w0.y = tf32r(oacc[mi][ni][1]);
            float2 w1; w1.x = tf32r(oacc[mi][ni][2]); w1.y = tf32r(oacc[mi][ni][3]);
            *(float2*)&vatt[((size_t)(b * Sz + r0)) * Dz + c] = w0;
            *(float2*)&vatt[((size_t)(b * Sz + r0 + 8)) * Dz + c] = w1;
        }
    }
}

// ---------------- fused residual add + LayerNorm (single pass, shfl reduce) ----------------
__global__ __launch_bounds__(256)
void ln_add(const float* __restrict__ x, const float* __restrict__ y,
            const float* __restrict__ g, const float* __restrict__ bt,
            float* __restrict__ out, float* __restrict__ out_r)
{
    __shared__ float wsum[8], wsq[8];
    const int r = blockIdx.x, tid = threadIdx.x;
    const int lane = tid & 31, warp = tid >> 5;

    float4 x4 = *(const float4*)&x[(size_t)r * Dz + tid * 4];
    float4 y4 = *(const float4*)&y[(size_t)r * Dz + tid * 4];
    float t0 = x4.x + y4.x, t1 = x4.y + y4.y, t2 = x4.z + y4.z, t3 = x4.w + y4.w;

    float s = t0 + t1 + t2 + t3;
    float q = t0 * t0 + t1 * t1 + t2 * t2 + t3 * t3;
    #pragma unroll
    for (int m = 16; m > 0; m >>= 1) {
        s += __shfl_xor_sync(0xffffffffu, s, m);
        q += __shfl_xor_sync(0xffffffffu, q, m);
    }
    if (lane == 0) { wsum[warp] = s; wsq[warp] = q; }
    __syncthreads();
    if (tid < 32) {
        float s8 = (lane < 8) ? wsum[lane] : 0.0f;
        float q8 = (lane < 8) ? wsq[lane] : 0.0f;
        #pragma unroll
        for (int m = 4; m > 0; m >>= 1) {
            s8 += __shfl_xor_sync(0xffffffffu, s8, m);
            q8 += __shfl_xor_sync(0xffffffffu, q8, m);
        }
        if (lane == 0) { wsum[0] = s8; wsq[0] = q8; }
    }
    __syncthreads();

    const float mu = wsum[0] * (1.0f / Dz);
    const float var = wsq[0] * (1.0f / Dz) - mu * mu;
    const float rstd = rsqrtf(var + 1e-5f);

    float4 g4 = *(const float4*)&g[tid * 4];
    float4 b4 = *(const float4*)&bt[tid * 4];
    float4 o;
    o.x = g4.x * (t0 - mu) * rstd + b4.x;
    o.y = g4.y * (t1 - mu) * rstd + b4.y;
    o.z = g4.z * (t2 - mu) * rstd + b4.z;
    o.w = g4.w * (t3 - mu) * rstd + b4.w;
    *(float4*)&out[(size_t)r * Dz + tid * 4] = o;
    if (out_r) {
        float4 orr;
        orr.x = tf32r(o.x); orr.y = tf32r(o.y); orr.z = tf32r(o.z); orr.w = tf32r(o.w);
        *(float4*)&out_r[(size_t)r * Dz + tid * 4] = orr;
    }
}

// ---------------- host launcher ----------------
extern "C" void kernel_launch(void* const* d_in, const int* in_sizes, int n_in,
                              void* d_out, int out_size)
{
    const float* Q   = (const float*)d_in[0];
    const float* Kin = (const float*)d_in[1];
    const float* Vin = (const float*)d_in[2];
    const float* W_q = (const float*)d_in[4];
    const float* W_k = (const float*)d_in[5];
    const float* W_v = (const float*)d_in[6];
    const float* W_o = (const float*)d_in[7];
    const float* w1  = (const float*)d_in[8];
    const float* b1  = (const float*)d_in[9];
    const float* w2  = (const float*)d_in[10];
    const float* b2  = (const float*)d_in[11];
    const float* lng = (const float*)d_in[12];
    const float* lnb = (const float*)d_in[13];

    float *qp, *kp, *vp, *vattp, *Xp, *Xr, *Qr, *h1p, *tp, *wr, *attfb;
    cudaGetSymbolAddress((void**)&qp, g_q);
    cudaGetSymbolAddress((void**)&kp, g_k);
    cudaGetSymbolAddress((void**)&vp, g_v);
    cudaGetSymbolAddress((void**)&vattp, g_vatt);
    cudaGetSymbolAddress((void**)&Xp, g_X);
    cudaGetSymbolAddress((void**)&Xr, g_xr);
    cudaGetSymbolAddress((void**)&Qr, g_qr);
    cudaGetSymbolAddress((void**)&h1p, g_h1);
    cudaGetSymbolAddress((void**)&tp, g_t);
    cudaGetSymbolAddress((void**)&wr, g_wr);
    cudaGetSymbolAddress((void**)&attfb, g_attfb);

    float* wq_r = wr;
    float* wk_r = wr + 1 * (size_t)Dz * Dz;
    float* wv_r = wr + 2 * (size_t)Dz * Dz;
    float* wo_r = wr + 3 * (size_t)Dz * Dz;
    float* w1_r = wr + 4 * (size_t)Dz * Dz;
    float* w2_r = wr + 5 * (size_t)Dz * Dz;
    float* Kr = h1p;   // temp rounded K input (g_h1 free until FFN)
    float* Vr = tp;    // temp rounded V input (g_t free until Wo GEMM)

    const int SM_NN = 2 * (ASTG + 4352) * 4;   // 71680
    const int SM_NT = 2 * (ASTG + 4608) * 4;   // 73728
    cudaFuncSetAttribute(attn_fused, cudaFuncAttributeMaxDynamicSharedMemorySize, AT_SMEM);
    cudaFuncSetAttribute(tgemm2<false,0,true>,  cudaFuncAttributeMaxDynamicSharedMemorySize, SM_NN);
    cudaFuncSetAttribute(tgemm2<false,0,false>, cudaFuncAttributeMaxDynamicSharedMemorySize, SM_NN);
    cudaFuncSetAttribute(tgemm2<true,1,true>,   cudaFuncAttributeMaxDynamicSharedMemorySize, SM_NT);
    cudaFuncSetAttribute(tgemm2<true,2,false>,  cudaFuncAttributeMaxDynamicSharedMemorySize, SM_NT);

    const size_t OUT_MAIN = (size_t)Mz * Dz;            // 8388608
    const size_t ATT_N    = (size_t)BHz * Sz * Sz;      // 134217728
    float* outp = (float*)d_out;
    float* att  = ((size_t)out_size >= OUT_MAIN + ATT_N) ? (outp + OUT_MAIN) : attfb;

    dim3 gg(Dz / 128, Mz / 128);
    dim3 gb(256);
    dim3 ag(BHz, 8);
    const int M4 = (Mz * Dz) / 4, W4 = (Dz * Dz) / 4;

    // pre-round activations + weights once (semantically identical to per-tile cvt)
    roundcopy3<<<dim3(M4 / 256, 3), 256>>>(
        (const float4*)Q, (const float4*)Kin, (const float4*)Vin,
        (float4*)Qr, (float4*)Kr, (float4*)Vr);
    roundcopy6<<<dim3(W4 / 256, 6), 256>>>(
        (const float4*)W_q, (const float4*)W_k, (const float4*)W_v,
        (const float4*)W_o, (const float4*)w1, (const float4*)w2,
        (float4*)wr, W4);   // seg in float4 units

    // QKV projections (separate launches — merged variant regressed in R11)
    tgemm2<false,0,true><<<gg, gb, SM_NN>>>(Qr, wq_r, nullptr, qp, Mz, Dz, Dz);
    tgemm2<false,0,true><<<gg, gb, SM_NN>>>(Kr, wk_r, nullptr, kp, Mz, Dz, Dz);
    tgemm2<false,0,true><<<gg, gb, SM_NN>>>(Vr, wv_r, nullptr, vp, Mz, Dz, Dz);
    // fused flash attention (vatt rounded in epilogue)
    attn_fused<<<ag, gb, AT_SMEM>>>(qp, kp, vp, att, vattp);
    // output projection + first residual LN (residual uses ORIGINAL Q)
    tgemm2<false,0,false><<<gg, gb, SM_NN>>>(vattp, wo_r, nullptr, tp, Mz, Dz, Dz);
    ln_add<<<Mz, 256>>>(Q, tp, lng, lnb, Xp, Xr);
    // FFN
    tgemm2<true,1,true><<<gg, gb, SM_NT>>>(Xr, w1_r, b1, h1p, Mz, Dz, Dz);
    tgemm2<true,2,false><<<gg, gb, SM_NT>>>(h1p, w2_r, b2, tp, Mz, Dz, Dz);
    // final residual LN -> d_out
    ln_add<<<Mz, 256>>>(Xp, tp, lng, lnb, outp, nullptr);
}

// round 13
// speedup vs baseline: 1.5173x; 1.0344x over previous
#include <cuda_runtime.h>
#include <math.h>
#include <stdint.h>

// Problem constants
#define Bz 8
#define Sz 1024
#define Dz 1024
#define Hz 16
#define Mz (Bz*Sz)          // 8192 rows
#define BHz (Bz*Hz)         // 128 (b,h) pairs

// ---------------- scratch (device globals: no allocation allowed) ----------------
__device__ float g_q[Mz*Dz];
__device__ float g_k[Mz*Dz];
__device__ float g_v[Mz*Dz];
__device__ float g_vatt[Mz*Dz];
__device__ float g_X[Mz*Dz];
__device__ float g_xr[Mz*Dz];
__device__ float g_qr[Mz*Dz];
__device__ float g_h1[Mz*Dz];       // FFN hidden; also temp rounded-K before attention
__device__ float g_t[Mz*Dz];        // GEMM temp; also temp rounded-V before attention
__device__ float g_wr[6*Dz*Dz];     // pre-rounded weights: Wq Wk Wv Wo w1 w2
__device__ float g_attfb[134217728];

__device__ __forceinline__ float gelu_exact(float x) {
    return 0.5f * x * (1.0f + erff(x * 0.70710678118654752f));
}

__device__ __forceinline__ float tf32r(float x) {
    uint32_t u;
    asm("cvt.rna.tf32.f32 %0, %1;" : "=r"(u) : "f"(x));
    return __uint_as_float(u);
}

__device__ __forceinline__ void mma8(float* c, const uint32_t* a, uint32_t b0, uint32_t b1) {
    asm("mma.sync.aligned.m16n8k8.row.col.f32.tf32.tf32.f32 "
        "{%0,%1,%2,%3}, {%4,%5,%6,%7}, {%8,%9}, {%0,%1,%2,%3};"
        : "+f"(c[0]), "+f"(c[1]), "+f"(c[2]), "+f"(c[3])
        : "r"(a[0]), "r"(a[1]), "r"(a[2]), "r"(a[3]), "r"(b0), "r"(b1));
}

__device__ __forceinline__ void cpa16(uint32_t s, const void* g) {
    asm volatile("cp.async.ca.shared.global [%0], [%1], 16;\n" :: "r"(s), "l"(g));
}

// ldmatrix on 32-bit data: lane l receives element (row l/4, col l%4) of each 8x4 f32 tile.
__device__ __forceinline__ void ldsm4(uint32_t* r, uint32_t addr) {
    asm volatile("ldmatrix.sync.aligned.m8n8.x4.shared.b16 {%0,%1,%2,%3}, [%4];"
        : "=r"(r[0]), "=r"(r[1]), "=r"(r[2]), "=r"(r[3]) : "r"(addr));
}
__device__ __forceinline__ void ldsm2(uint32_t& r0, uint32_t& r1, uint32_t addr) {
    asm volatile("ldmatrix.sync.aligned.m8n8.x2.shared.b16 {%0,%1}, [%2];"
        : "=r"(r0), "=r"(r1) : "r"(addr));
}

// ---------------- batched tf32 round-copy (grid.y = segment) ----------------
__global__ void roundcopy3(const float4* __restrict__ s0, const float4* __restrict__ s1,
                           const float4* __restrict__ s2,
                           float4* __restrict__ d0, float4* __restrict__ d1,
                           float4* __restrict__ d2)
{
    int i = blockIdx.x * blockDim.x + threadIdx.x;
    const float4* s = (blockIdx.y == 0) ? s0 : (blockIdx.y == 1) ? s1 : s2;
    float4* d = (blockIdx.y == 0) ? d0 : (blockIdx.y == 1) ? d1 : d2;
    float4 v = s[i];
    float4 t;
    t.x = tf32r(v.x); t.y = tf32r(v.y); t.z = tf32r(v.z); t.w = tf32r(v.w);
    d[i] = t;
}

// seg is the per-matrix stride IN FLOAT4 UNITS (Dz*Dz/4).
__global__ void roundcopy6(const float4* __restrict__ s0, const float4* __restrict__ s1,
                           const float4* __restrict__ s2, const float4* __restrict__ s3,
                           const float4* __restrict__ s4, const float4* __restrict__ s5,
                           float4* __restrict__ dst, int seg)
{
    int i = blockIdx.x * blockDim.x + threadIdx.x;
    const float4* s;
    switch (blockIdx.y) {
        case 0: s = s0; break; case 1: s = s1; break; case 2: s = s2; break;
        case 3: s = s3; break; case 4: s = s4; break; default: s = s5; break;
    }
    float4 v = s[i];
    float4 t;
    t.x = tf32r(v.x); t.y = tf32r(v.y); t.z = tf32r(v.z); t.w = tf32r(v.w);
    dst[(size_t)blockIdx.y * seg + i] = t;
}

// ---------------- tf32 tensor-core GEMM (cp.async 2-stage, k32, ldmatrix frags) ----------
// Inputs pre-rounded to tf32. A: [M,K] row-major.
// TB=false: B [K,N] (NN). TB=true: B [N,K] (NT, C = A@B^T).
// 128x128x32 tiles, 256 threads (8 warps 2x4), warp tile 64x32 via m16n8k8.
#define ASTG 4608            // 128*36 floats per stage
template<bool TB, int EPI, bool RND>   // EPI: 0 none, 1 bias+gelu, 2 bias
__global__ __launch_bounds__(256, 2)
void tgemm2(const float* __restrict__ A, const float* __restrict__ Bm,
            const float* __restrict__ bias, float* __restrict__ C,
            int M, int N, int K)
{
    constexpr int BSTG = TB ? 4608 : 4352;   // [n][k]s36 : [k][n]s136
    extern __shared__ float sh[];
    float* As = sh;
    float* Bs = sh + 2 * ASTG;

    const int tid = threadIdx.x;
    const int lane = tid & 31, warp = tid >> 5;
    const int wm = (warp >> 2) * 64, wn = (warp & 3) * 32;
    const int g = lane >> 2, tg = lane & 3;
    const int bx = blockIdx.x * 128, by = blockIdx.y * 128;

    const uint32_t sa = (uint32_t)__cvta_generic_to_shared(As);
    const uint32_t sb = (uint32_t)__cvta_generic_to_shared(Bs);

    // ldmatrix per-lane addressing: 4 submatrices (+0r,+0c)(+8r,+0c)(+0r,+4c)(+8r,+4c)
    const int lrow = (lane & 7) + ((lane >> 3) & 1) * 8;   // row within 16
    const int lcol = (lane >> 4) << 2;                     // 0 or 4
    const uint32_t aoff    = (uint32_t)(((wm + lrow) * 36 + lcol) * 4);
    const uint32_t boff_tb = (uint32_t)(((wn + (lane & 7)) * 36 + (((lane >> 3) & 1) << 2)) * 4);

    float acc[4][4][4];
    #pragma unroll
    for (int mi = 0; mi < 4; mi++)
        #pragma unroll
        for (int ni = 0; ni < 4; ni++)
            #pragma unroll
            for (int q = 0; q < 4; q++) acc[mi][ni][q] = 0.0f;

    int ar[4], ac[4], br[4], bc[4];
    #pragma unroll
    for (int u = 0; u < 4; u++) {
        int f = tid + u * 256;
        ar[u] = f >> 3; ac[u] = (f & 7) * 4;               // A: 128 rows x 8 chunks
        if (TB) { br[u] = f >> 3; bc[u] = (f & 7) * 4; }   // B: 128 rows x 8 chunks
        else    { br[u] = f >> 5; bc[u] = (f & 31) * 4; }  // B: 32 rows x 32 chunks
    }

    const int nk = K >> 5;

    // prologue: stage 0
    {
        #pragma unroll
        for (int u = 0; u < 4; u++)
            cpa16(sa + (uint32_t)(ar[u] * 36 + ac[u]) * 4,
                  &A[(size_t)(by + ar[u]) * K + ac[u]]);
        if (TB) {
            #pragma unroll
            for (int u = 0; u < 4; u++)
                cpa16(sb + (uint32_t)(br[u] * 36 + bc[u]) * 4,
                      &Bm[(size_t)(bx + br[u]) * K + bc[u]]);
        } else {
            #pragma unroll
            for (int u = 0; u < 4; u++)
                cpa16(sb + (uint32_t)(br[u] * 136 + bc[u]) * 4,
                      &Bm[(size_t)(br[u]) * N + bx + bc[u]]);
        }
        asm volatile("cp.async.commit_group;\n" ::);
    }

    for (int kt = 0; kt < nk; kt++) {
        const int p = kt & 1;
        if (kt + 1 < nk) {
            const int ko = (kt + 1) * 32;
            const uint32_t pa = sa + (uint32_t)(((kt + 1) & 1) * ASTG) * 4;
            const uint32_t pb = sb + (uint32_t)(((kt + 1) & 1) * BSTG) * 4;
            #pragma unroll
            for (int u = 0; u < 4; u++)
                cpa16(pa + (uint32_t)(ar[u] * 36 + ac[u]) * 4,
                      &A[(size_t)(by + ar[u]) * K + ko + ac[u]]);
            if (TB) {
                #pragma unroll
                for (int u = 0; u < 4; u++)
                    cpa16(pb + (uint32_t)(br[u] * 36 + bc[u]) * 4,
                          &Bm[(size_t)(bx + br[u]) * K + ko + bc[u]]);
            } else {
                #pragma unroll
                for (int u = 0; u < 4; u++)
                    cpa16(pb + (uint32_t)(br[u] * 136 + bc[u]) * 4,
                          &Bm[(size_t)(ko + br[u]) * N + bx + bc[u]]);
            }
            asm volatile("cp.async.commit_group;\n" ::);
            asm volatile("cp.async.wait_group 1;\n" ::);
        } else {
            asm volatile("cp.async.wait_group 0;\n" ::);
        }
        __syncthreads();

        const uint32_t pA = sa + (uint32_t)(p * ASTG) * 4 + aoff;
        const uint32_t pB = sb + (uint32_t)(p * BSTG) * 4;
        const float* Bp = Bs + p * BSTG;
        #pragma unroll
        for (int k8 = 0; k8 < 32; k8 += 8) {
            uint32_t af[4][4];
            #pragma unroll
            for (int mi = 0; mi < 4; mi++)
                ldsm4(af[mi], pA + (uint32_t)((mi * 16 * 36 + k8) * 4));
            #pragma unroll
            for (int ni = 0; ni < 4; ni++) {
                uint32_t b0, b1;
                if (TB) {
                    ldsm2(b0, b1, pB + boff_tb + (uint32_t)((ni * 8 * 36 + k8) * 4));
                } else {
                    const int c0 = wn + ni * 8 + g;
                    b0 = __float_as_uint(Bp[(k8 + tg) * 136 + c0]);
                    b1 = __float_as_uint(Bp[(k8 + 4 + tg) * 136 + c0]);
                }
                #pragma unroll
                for (int mi = 0; mi < 4; mi++) mma8(acc[mi][ni], af[mi], b0, b1);
            }
        }
        __syncthreads();
    }

    #pragma unroll
    for (int mi = 0; mi < 4; mi++) {
        const int r0 = by + wm + mi * 16 + g;
        #pragma unroll
        for (int ni = 0; ni < 4; ni++) {
            const int c0 = bx + wn + ni * 8 + 2 * tg;
            float v0 = acc[mi][ni][0], v1 = acc[mi][ni][1];
            float v2 = acc[mi][ni][2], v3 = acc[mi][ni][3];
            if (EPI != 0) {
                float bb0 = bias[c0], bb1 = bias[c0 + 1];
                v0 += bb0; v1 += bb1; v2 += bb0; v3 += bb1;
            }
            if (EPI == 1) {
                v0 = gelu_exact(v0); v1 = gelu_exact(v1);
                v2 = gelu_exact(v2); v3 = gelu_exact(v3);
            }
            if (RND) {
                v0 = tf32r(v0); v1 = tf32r(v1); v2 = tf32r(v2); v3 = tf32r(v3);
            }
            float2 w0; w0.x = v0; w0.y = v1;
            float2 w1; w1.x = v2; w1.y = v3;
            *(float2*)&C[(size_t)r0 * N + c0] = w0;
            *(float2*)&C[(size_t)(r0 + 8) * N + c0] = w1;
        }
    }
}

// ---------------- fused tensor-core flash attention (unchanged, known good) ----------------
#define AT_SMEM 107520
__global__ __launch_bounds__(256, 2)
void attn_fused(const float* __restrict__ qp, const float* __restrict__ kp,
                const float* __restrict__ vp, float* __restrict__ att,
                float* __restrict__ vatt)
{
    extern __shared__ float sh[];
    float* Qs   = sh;                    // [128][68]
    float* Ks   = sh + 128 * 68;         // [64][68]
    float* Vs   = Ks + 64 * 68;          // [64][68]
    float* Ps   = Vs + 64 * 68;          // [128][68]
    float* smP  = Ps + 128 * 68;         // [128][4]
    float* sm_m = smP + 512;             // [128]
    float* sm_il= sm_m + 128;            // [128]

    const int bh = blockIdx.x, b = bh >> 4, h = bh & 15;
    const int qt = 7 - blockIdx.y;
    const int qbase = qt * 128;
    const int tid = threadIdx.x;
    const int lane = tid & 31, warp = tid >> 5;
    const int wy = warp >> 1, wx = warp & 1;
    const int wm = wy * 32;
    const int g = lane >> 2, tg = lane & 3;
    const float scale = 1.0f / (8.0f + 1e-6f);

    const float* qg = qp + ((size_t)(b * Sz + qbase)) * Dz + h * 64;
    #pragma unroll
    for (int u = 0; u < 8; u++) {
        int f = tid + u * 256;
        int r = f >> 4, c4 = (f & 15) * 4;
        *(float4*)&Qs[r * 68 + c4] = *(const float4*)&qg[(size_t)r * Dz + c4];
    }

    float* ab = att + (size_t)bh * Sz * Sz;
    {
        float4 z; z.x = z.y = z.z = z.w = 0.0f;
        for (int j2 = 2 * qt + 2; j2 < 16; j2++) {
            const int kb = j2 * 64;
            #pragma unroll
            for (int u = 0; u < 8; u++) {
                int f = tid + u * 256;
                int r = f >> 4, c4 = (f & 15) * 4;
                *(float4*)&ab[(size_t)(qbase + r) * Sz + kb + c4] = z;
            }
        }
    }

    const int jmax = 2 * qt + 1;
    float run_m[4], run_l[4];
    #pragma unroll
    for (int s = 0; s < 4; s++) { run_m[s] = -1e30f; run_l[s] = 0.0f; }

    // ---------------- phase 1: softmax stats ----------------
    for (int jt = 0; jt <= jmax; jt++) {
        const int kbase = jt * 64;
        __syncthreads();
        const float* kg = kp + ((size_t)(b * Sz + kbase)) * Dz + h * 64;
        #pragma unroll
        for (int u = 0; u < 4; u++) {
            int f = tid + u * 256;
            int r = f >> 4, c4 = (f & 15) * 4;
            *(float4*)&Ks[r * 68 + c4] = *(const float4*)&kg[(size_t)r * Dz + c4];
        }
        __syncthreads();

        float sacc[2][4][4];
        #pragma unroll
        for (int mi = 0; mi < 2; mi++)
            #pragma unroll
            for (int ni = 0; ni < 4; ni++)
                #pragma unroll
                for (int q = 0; q < 4; q++) sacc[mi][ni][q] = 0.0f;

        #pragma unroll
        for (int k8 = 0; k8 < 64; k8 += 8) {
            uint32_t af[2][4];
            #pragma unroll
            for (int mi = 0; mi < 2; mi++) {
                const int r0 = (wm + mi * 16 + g) * 68 + k8 + tg;
                af[mi][0] = __float_as_uint(Qs[r0]);
                af[mi][1] = __float_as_uint(Qs[r0 + 8 * 68]);
                af[mi][2] = __float_as_uint(Qs[r0 + 4]);
                af[mi][3] = __float_as_uint(Qs[r0 + 8 * 68 + 4]);
            }
            #pragma unroll
            for (int ni = 0; ni < 4; ni++) {
                const int cb = (wx * 32 + ni * 8 + g) * 68 + k8 + tg;
                uint32_t b0 = __float_as_uint(Ks[cb]);
                uint32_t b1 = __float_as_uint(Ks[cb + 4]);
                mma8(sacc[0][ni], af[0], b0, b1);
                mma8(sacc[1][ni], af[1], b0, b1);
            }
        }

        const bool msk = (jt >= 2 * qt);
        #pragma unroll
        for (int mi = 0; mi < 2; mi++) {
            #pragma unroll
            for (int hf = 0; hf < 2; hf++) {
                const int s = mi * 2 + hf;
                const int rowg = qbase + wm + mi * 16 + hf * 8 + g;
                float vv[8];
                float lm = run_m[s];
                #pragma unroll
                for (int ni = 0; ni < 4; ni++) {
                    #pragma unroll
                    for (int q = 0; q < 2; q++) {
                        float sv = sacc[mi][ni][hf * 2 + q] * scale;
                        if (msk && (kbase + wx * 32 + ni * 8 + 2 * tg + q > rowg)) sv = -1e30f;
                        vv[ni * 2 + q] = sv;
                        lm = fmaxf(lm, sv);
                    }
                }
                float al = 0.0f;
                #pragma unroll
                for (int idx = 0; idx < 8; idx++) al += __expf(vv[idx] - lm);
                run_l[s] = run_l[s] * __expf(run_m[s] - lm) + al;
                run_m[s] = lm;
            }
        }
    }

    #pragma unroll
    for (int s = 0; s < 4; s++) {
        float m = run_m[s], l = run_l[s];
        #pragma unroll
        for (int mk = 1; mk < 4; mk <<= 1) {
            float om = __shfl_xor_sync(0xffffffffu, m, mk);
            float ol = __shfl_xor_sync(0xffffffffu, l, mk);
            float mn = fmaxf(m, om);
            l = l * __expf(m - mn) + ol * __expf(om - mn);
            m = mn;
        }
        run_m[s] = m; run_l[s] = l;
    }
    if (tg == 0) {
        #pragma unroll
        for (int s = 0; s < 4; s++) {
            int row = wm + (s >> 1) * 16 + (s & 1) * 8 + g;
            smP[row * 4 + wx * 2]     = run_m[s];
            smP[row * 4 + wx * 2 + 1] = run_l[s];
        }
    }
    __syncthreads();
    if (tid < 128) {
        float m0 = smP[tid * 4], l0 = smP[tid * 4 + 1];
        float m1 = smP[tid * 4 + 2], l1 = smP[tid * 4 + 3];
        float mn = fmaxf(m0, m1);
        float l = l0 * __expf(m0 - mn) + l1 * __expf(m1 - mn);
        sm_m[tid] = mn;
        sm_il[tid] = 1.0f / l;
    }
    __syncthreads();

    float m_s[4], il_s[4];
    #pragma unroll
    for (int s = 0; s < 4; s++) {
        int row = wm + (s >> 1) * 16 + (s & 1) * 8 + g;
        m_s[s] = sm_m[row];
        il_s[s] = sm_il[row];
    }

    float oacc[2][4][4];
    #pragma unroll
    for (int mi = 0; mi < 2; mi++)
        #pragma unroll
        for (int ni = 0; ni < 4; ni++)
            #pragma unroll
            for (int q = 0; q < 4; q++) oacc[mi][ni][q] = 0.0f;

    // ---------------- phase 2: P write + P@V ----------------
    for (int jt = 0; jt <= jmax; jt++) {
        const int kbase = jt * 64;
        __syncthreads();
        const float* kg = kp + ((size_t)(b * Sz + kbase)) * Dz + h * 64;
        const float* vg = vp + ((size_t)(b * Sz + kbase)) * Dz + h * 64;
        #pragma unroll
        for (int u = 0; u < 4; u++) {
            int f = tid + u * 256;
            int r = f >> 4, c4 = (f & 15) * 4;
            *(float4*)&Ks[r * 68 + c4] = *(const float4*)&kg[(size_t)r * Dz + c4];
            *(float4*)&Vs[r * 68 + c4] = *(const float4*)&vg[(size_t)r * Dz + c4];
        }
        __syncthreads();

        float sacc[2][4][4];
        #pragma unroll
        for (int mi = 0; mi < 2; mi++)
            #pragma unroll
            for (int ni = 0; ni < 4; ni++)
                #pragma unroll
                for (int q = 0; q < 4; q++) sacc[mi][ni][q] = 0.0f;

        #pragma unroll
        for (int k8 = 0; k8 < 64; k8 += 8) {
            uint32_t af[2][4];
            #pragma unroll
            for (int mi = 0; mi < 2; mi++) {
                const int r0 = (wm + mi * 16 + g) * 68 + k8 + tg;
                af[mi][0] = __float_as_uint(Qs[r0]);
                af[mi][1] = __float_as_uint(Qs[r0 + 8 * 68]);
                af[mi][2] = __float_as_uint(Qs[r0 + 4]);
                af[mi][3] = __float_as_uint(Qs[r0 + 8 * 68 + 4]);
            }
            #pragma unroll
            for (int ni = 0; ni < 4; ni++) {
                const int cb = (wx * 32 + ni * 8 + g) * 68 + k8 + tg;
                uint32_t b0 = __float_as_uint(Ks[cb]);
                uint32_t b1 = __float_as_uint(Ks[cb + 4]);
                mma8(sacc[0][ni], af[0], b0, b1);
                mma8(sacc[1][ni], af[1], b0, b1);
            }
        }

        const bool msk = (jt >= 2 * qt);
        #pragma unroll
        for (int mi = 0; mi < 2; mi++) {
            #pragma unroll
            for (int hf = 0; hf < 2; hf++) {
                const int s = mi * 2 + hf;
                const int rowl = wm + mi * 16 + hf * 8 + g;
                const int rowg = qbase + rowl;
                const float mm = m_s[s], il = il_s[s];
                #pragma unroll
                for (int ni = 0; ni < 4; ni++) {
                    const int col0 = kbase + wx * 32 + ni * 8 + 2 * tg;
                    float sv0 = sacc[mi][ni][hf * 2] * scale;
                    float sv1 = sacc[mi][ni][hf * 2 + 1] * scale;
                    float p0 = (msk && (col0 > rowg)) ? 0.0f : __expf(sv0 - mm) * il;
                    float p1 = (msk && (col0 + 1 > rowg)) ? 0.0f : __expf(sv1 - mm) * il;
                    float2 w; w.x = p0; w.y = p1;
                    *(float2*)&Ps[rowl * 68 + wx * 32 + ni * 8 + 2 * tg] = w;
                }
            }
        }
        __syncthreads();

        #pragma unroll
        for (int k8 = 0; k8 < 64; k8 += 8) {
            uint32_t pa[2][4];
            #pragma unroll
            for (int mi = 0; mi < 2; mi++) {
                const int r0 = (wm + mi * 16 + g) * 68 + k8 + tg;
                pa[mi][0] = __float_as_uint(tf32r(Ps[r0]));
                pa[mi][1] = __float_as_uint(tf32r(Ps[r0 + 8 * 68]));
                pa[mi][2] = __float_as_uint(tf32r(Ps[r0 + 4]));
                pa[mi][3] = __float_as_uint(tf32r(Ps[r0 + 8 * 68 + 4]));
            }
            #pragma unroll
            for (int ni = 0; ni < 4; ni++) {
                const int c0 = wx * 32 + ni * 8 + g;
                uint32_t b0 = __float_as_uint(Vs[(k8 + tg) * 68 + c0]);
                uint32_t b1 = __float_as_uint(Vs[(k8 + 4 + tg) * 68 + c0]);
                mma8(oacc[0][ni], pa[0], b0, b1);
                mma8(oacc[1][ni], pa[1], b0, b1);
            }
        }

        #pragma unroll
        for (int u = 0; u < 8; u++) {
            int f = tid + u * 256;
            int r = f >> 4, c4 = (f & 15) * 4;
            *(float4*)&ab[(size_t)(qbase + r) * Sz + kbase + c4] = *(float4*)&Ps[r * 68 + c4];
        }
    }

    // write v_att rounded (feeds Wo GEMM which expects tf32 inputs)
    #pragma unroll
    for (int mi = 0; mi < 2; mi++) {
        const int r0 = qbase + wm + mi * 16 + g;
        #pragma unroll
        for (int ni = 0; ni < 4; ni++) {
            const int c = h * 64 + wx * 32 + ni * 8 + 2 * tg;
            float2 w0; w0.x = tf32r(oacc[mi][ni][0]); w0.y = tf32r(oacc[mi][ni][1]);
            float2 w1; w1.x = tf32r(oacc[mi][ni][2]); w1.y = tf32r(oacc[mi][ni][3]);
            *(float2*)&vatt[((size_t)(b * Sz + r0)) * Dz + c] = w0;
            *(float2*)&vatt[((size_t)(b * Sz + r0 + 8)) * Dz + c] = w1;
        }
    }
}

// ---------------- fused residual add + LayerNorm (single pass, shfl reduce) ----------------
__global__ __launch_bounds__(256)
void ln_add(const float* __restrict__ x, const float* __restrict__ y,
            const float* __restrict__ g, const float* __restrict__ bt,
            float* __restrict__ out, float* __restrict__ out_r)
{
    __shared__ float wsum[8], wsq[8];
    const int r = blockIdx.x, tid = threadIdx.x;
    const int lane = tid & 31, warp = tid >> 5;

    float4 x4 = *(const float4*)&x[(size_t)r * Dz + tid * 4];
    float4 y4 = *(const float4*)&y[(size_t)r * Dz + tid * 4];
    float t0 = x4.x + y4.x, t1 = x4.y + y4.y, t2 = x4.z + y4.z, t3 = x4.w + y4.w;

    float s = t0 + t1 + t2 + t3;
    float q = t0 * t0 + t1 * t1 + t2 * t2 + t3 * t3;
    #pragma unroll
    for (int m = 16; m > 0; m >>= 1) {
        s += __shfl_xor_sync(0xffffffffu, s, m);
        q += __shfl_xor_sync(0xffffffffu, q, m);
    }
    if (lane == 0) { wsum[warp] = s; wsq[warp] = q; }
    __syncthreads();
    if (tid < 32) {
        float s8 = (lane < 8) ? wsum[lane] : 0.0f;
        float q8 = (lane < 8) ? wsq[lane] : 0.0f;
        #pragma unroll
        for (int m = 4; m > 0; m >>= 1) {
            s8 += __shfl_xor_sync(0xffffffffu, s8, m);
            q8 += __shfl_xor_sync(0xffffffffu, q8, m);
        }
        if (lane == 0) { wsum[0] = s8; wsq[0] = q8; }
    }
    __syncthreads();

    const float mu = wsum[0] * (1.0f / Dz);
    const float var = wsq[0] * (1.0f / Dz) - mu * mu;
    const float rstd = rsqrtf(var + 1e-5f);

    float4 g4 = *(const float4*)&g[tid * 4];
    float4 b4 = *(const float4*)&bt[tid * 4];
    float4 o;
    o.x = g4.x * (t0 - mu) * rstd + b4.x;
    o.y = g4.y * (t1 - mu) * rstd + b4.y;
    o.z = g4.z * (t2 - mu) * rstd + b4.z;
    o.w = g4.w * (t3 - mu) * rstd + b4.w;
    *(float4*)&out[(size_t)r * Dz + tid * 4] = o;
    if (out_r) {
        float4 orr;
        orr.x = tf32r(o.x); orr.y = tf32r(o.y); orr.z = tf32r(o.z); orr.w = tf32r(o.w);
        *(float4*)&out_r[(size_t)r * Dz + tid * 4] = orr;
    }
}

// ---------------- host launcher ----------------
extern "C" void kernel_launch(void* const* d_in, const int* in_sizes, int n_in,
                              void* d_out, int out_size)
{
    const float* Q   = (const float*)d_in[0];
    const float* Kin = (const float*)d_in[1];
    const float* Vin = (const float*)d_in[2];
    const float* W_q = (const float*)d_in[4];
    const float* W_k = (const float*)d_in[5];
    const float* W_v = (const float*)d_in[6];
    const float* W_o = (const float*)d_in[7];
    const float* w1  = (const float*)d_in[8];
    const float* b1  = (const float*)d_in[9];
    const float* w2  = (const float*)d_in[10];
    const float* b2  = (const float*)d_in[11];
    const float* lng = (const float*)d_in[12];
    const float* lnb = (const float*)d_in[13];

    float *qp, *kp, *vp, *vattp, *Xp, *Xr, *Qr, *h1p, *tp, *wr, *attfb;
    cudaGetSymbolAddress((void**)&qp, g_q);
    cudaGetSymbolAddress((void**)&kp, g_k);
    cudaGetSymbolAddress((void**)&vp, g_v);
    cudaGetSymbolAddress((void**)&vattp, g_vatt);
    cudaGetSymbolAddress((void**)&Xp, g_X);
    cudaGetSymbolAddress((void**)&Xr, g_xr);
    cudaGetSymbolAddress((void**)&Qr, g_qr);
    cudaGetSymbolAddress((void**)&h1p, g_h1);
    cudaGetSymbolAddress((void**)&tp, g_t);
    cudaGetSymbolAddress((void**)&wr, g_wr);
    cudaGetSymbolAddress((void**)&attfb, g_attfb);

    float* wq_r = wr;
    float* wk_r = wr + 1 * (size_t)Dz * Dz;
    float* wv_r = wr + 2 * (size_t)Dz * Dz;
    float* wo_r = wr + 3 * (size_t)Dz * Dz;
    float* w1_r = wr + 4 * (size_t)Dz * Dz;
    float* w2_r = wr + 5 * (size_t)Dz * Dz;
    float* Kr = h1p;   // temp rounded K input (g_h1 free until FFN)
    float* Vr = tp;    // temp rounded V input (g_t free until Wo GEMM)

    const int SM_NN = 2 * (ASTG + 4352) * 4;   // 71680
    const int SM_NT = 2 * (ASTG + 4608) * 4;   // 73728
    cudaFuncSetAttribute(attn_fused, cudaFuncAttributeMaxDynamicSharedMemorySize, AT_SMEM);
    cudaFuncSetAttribute(tgemm2<false,0,true>,  cudaFuncAttributeMaxDynamicSharedMemorySize, SM_NN);
    cudaFuncSetAttribute(tgemm2<false,0,false>, cudaFuncAttributeMaxDynamicSharedMemorySize, SM_NN);
    cudaFuncSetAttribute(tgemm2<true,1,true>,   cudaFuncAttributeMaxDynamicSharedMemorySize, SM_NT);
    cudaFuncSetAttribute(tgemm2<true,2,false>,  cudaFuncAttributeMaxDynamicSharedMemorySize, SM_NT);

    const size_t OUT_MAIN = (size_t)Mz * Dz;            // 8388608
    const size_t ATT_N    = (size_t)BHz * Sz * Sz;      // 134217728
    float* outp = (float*)d_out;
    float* att  = ((size_t)out_size >= OUT_MAIN + ATT_N) ? (outp + OUT_MAIN) : attfb;

    dim3 gg(Dz / 128, Mz / 128);
    dim3 gb(256);
    dim3 ag(BHz, 8);
    const int M4 = (Mz * Dz) / 4, W4 = (Dz * Dz) / 4;

    // pre-round activations + weights once (semantically identical to per-tile cvt)
    roundcopy3<<<dim3(M4 / 256, 3), 256>>>(
        (const float4*)Q, (const float4*)Kin, (const float4*)Vin,
        (float4*)Qr, (float4*)Kr, (float4*)Vr);
    roundcopy6<<<dim3(W4 / 256, 6), 256>>>(
        (const float4*)W_q, (const float4*)W_k, (const float4*)W_v,
        (const float4*)W_o, (const float4*)w1, (const float4*)w2,
        (float4*)wr, W4);   // seg in float4 units

    // QKV projections
    tgemm2<false,0,true><<<gg, gb, SM_NN>>>(Qr, wq_r, nullptr, qp, Mz, Dz, Dz);
    tgemm2<false,0,true><<<gg, gb, SM_NN>>>(Kr, wk_r, nullptr, kp, Mz, Dz, Dz);
    tgemm2<false,0,true><<<gg, gb, SM_NN>>>(Vr, wv_r, nullptr, vp, Mz, Dz, Dz);
    // fused flash attention (vatt rounded in epilogue)
    attn_fused<<<ag, gb, AT_SMEM>>>(qp, kp, vp, att, vattp);
    // output projection + first residual LN (residual uses ORIGINAL Q)
    tgemm2<false,0,false><<<gg, gb, SM_NN>>>(vattp, wo_r, nullptr, tp, Mz, Dz, Dz);
    ln_add<<<Mz, 256>>>(Q, tp, lng, lnb, Xp, Xr);
    // FFN
    tgemm2<true,1,true><<<gg, gb, SM_NT>>>(Xr, w1_r, b1, h1p, Mz, Dz, Dz);
    tgemm2<true,2,false><<<gg, gb, SM_NT>>>(h1p, w2_r, b2, tp, Mz, Dz, Dz);
    // final residual LN -> d_out
    ln_add<<<Mz, 256>>>(Xp, tp, lng, lnb, outp, nullptr);
}

// round 14
// speedup vs baseline: 1.5429x; 1.0168x over previous
#include <cuda_runtime.h>
#include <math.h>
#include <stdint.h>

// Problem constants
#define Bz 8
#define Sz 1024
#define Dz 1024
#define Hz 16
#define Mz (Bz*Sz)          // 8192 rows
#define BHz (Bz*Hz)         // 128 (b,h) pairs

// ---------------- scratch (device globals: no allocation allowed) ----------------
__device__ float g_q[Mz*Dz];
__device__ float g_k[Mz*Dz];
__device__ float g_v[Mz*Dz];
__device__ float g_vatt[Mz*Dz];
__device__ float g_X[Mz*Dz];
__device__ float g_xr[Mz*Dz];
__device__ float g_qr[Mz*Dz];
__device__ float g_h1[Mz*Dz];       // FFN hidden; also temp rounded-K before attention
__device__ float g_t[Mz*Dz];        // GEMM temp; also temp rounded-V before attention
__device__ float g_wr[6*Dz*Dz];     // pre-rounded weights: Wq Wk Wv Wo w1 w2
__device__ float g_attfb[134217728];

__device__ __forceinline__ float gelu_exact(float x) {
    return 0.5f * x * (1.0f + erff(x * 0.70710678118654752f));
}

__device__ __forceinline__ float tf32r(float x) {
    uint32_t u;
    asm("cvt.rna.tf32.f32 %0, %1;" : "=r"(u) : "f"(x));
    return __uint_as_float(u);
}

__device__ __forceinline__ uint32_t tf32u(uint32_t x) {
    uint32_t u;
    asm("cvt.rna.tf32.f32 %0, %1;" : "=r"(u) : "f"(__uint_as_float(x)));
    return u;
}

__device__ __forceinline__ void mma8(float* c, const uint32_t* a, uint32_t b0, uint32_t b1) {
    asm("mma.sync.aligned.m16n8k8.row.col.f32.tf32.tf32.f32 "
        "{%0,%1,%2,%3}, {%4,%5,%6,%7}, {%8,%9}, {%0,%1,%2,%3};"
        : "+f"(c[0]), "+f"(c[1]), "+f"(c[2]), "+f"(c[3])
        : "r"(a[0]), "r"(a[1]), "r"(a[2]), "r"(a[3]), "r"(b0), "r"(b1));
}

__device__ __forceinline__ void cpa16(uint32_t s, const void* g) {
    asm volatile("cp.async.ca.shared.global [%0], [%1], 16;\n" :: "r"(s), "l"(g));
}

// ldmatrix on 32-bit data: lane l receives element (row l/4, col l%4) of each 8x4 f32 tile.
__device__ __forceinline__ void ldsm4(uint32_t* r, uint32_t addr) {
    asm volatile("ldmatrix.sync.aligned.m8n8.x4.shared.b16 {%0,%1,%2,%3}, [%4];"
        : "=r"(r[0]), "=r"(r[1]), "=r"(r[2]), "=r"(r[3]) : "r"(addr));
}
__device__ __forceinline__ void ldsm2(uint32_t& r0, uint32_t& r1, uint32_t addr) {
    asm volatile("ldmatrix.sync.aligned.m8n8.x2.shared.b16 {%0,%1}, [%2];"
        : "=r"(r0), "=r"(r1) : "r"(addr));
}

// ---------------- batched tf32 round-copy (grid.y = segment) ----------------
__global__ void roundcopy3(const float4* __restrict__ s0, const float4* __restrict__ s1,
                           const float4* __restrict__ s2,
                           float4* __restrict__ d0, float4* __restrict__ d1,
                           float4* __restrict__ d2)
{
    int i = blockIdx.x * blockDim.x + threadIdx.x;
    const float4* s = (blockIdx.y == 0) ? s0 : (blockIdx.y == 1) ? s1 : s2;
    float4* d = (blockIdx.y == 0) ? d0 : (blockIdx.y == 1) ? d1 : d2;
    float4 v = s[i];
    float4 t;
    t.x = tf32r(v.x); t.y = tf32r(v.y); t.z = tf32r(v.z); t.w = tf32r(v.w);
    d[i] = t;
}

// seg is the per-matrix stride IN FLOAT4 UNITS (Dz*Dz/4).
__global__ void roundcopy6(const float4* __restrict__ s0, const float4* __restrict__ s1,
                           const float4* __restrict__ s2, const float4* __restrict__ s3,
                           const float4* __restrict__ s4, const float4* __restrict__ s5,
                           float4* __restrict__ dst, int seg)
{
    int i = blockIdx.x * blockDim.x + threadIdx.x;
    const float4* s;
    switch (blockIdx.y) {
        case 0: s = s0; break; case 1: s = s1; break; case 2: s = s2; break;
        case 3: s = s3; break; case 4: s = s4; break; default: s = s5; break;
    }
    float4 v = s[i];
    float4 t;
    t.x = tf32r(v.x); t.y = tf32r(v.y); t.z = tf32r(v.z); t.w = tf32r(v.w);
    dst[(size_t)blockIdx.y * seg + i] = t;
}

// ---------------- tf32 tensor-core GEMM (cp.async 2-stage, k32, ldmatrix frags) ----------
// Inputs pre-rounded to tf32. A: [M,K] row-major.
// TB=false: B [K,N] (NN). TB=true: B [N,K] (NT, C = A@B^T).
// 128x128x32 tiles, 256 threads (8 warps 2x4), warp tile 64x32 via m16n8k8.
#define ASTG 4608            // 128*36 floats per stage
template<bool TB, int EPI, bool RND>   // EPI: 0 none, 1 bias+gelu, 2 bias
__global__ __launch_bounds__(256, 2)
void tgemm2(const float* __restrict__ A, const float* __restrict__ Bm,
            const float* __restrict__ bias, float* __restrict__ C,
            int M, int N, int K)
{
    constexpr int BSTG = TB ? 4608 : 4352;   // [n][k]s36 : [k][n]s136
    extern __shared__ float sh[];
    float* As = sh;
    float* Bs = sh + 2 * ASTG;

    const int tid = threadIdx.x;
    const int lane = tid & 31, warp = tid >> 5;
    const int wm = (warp >> 2) * 64, wn = (warp & 3) * 32;
    const int g = lane >> 2, tg = lane & 3;
    const int bx = blockIdx.x * 128, by = blockIdx.y * 128;

    const uint32_t sa = (uint32_t)__cvta_generic_to_shared(As);
    const uint32_t sb = (uint32_t)__cvta_generic_to_shared(Bs);

    // ldmatrix per-lane addressing: 4 submatrices (+0r,+0c)(+8r,+0c)(+0r,+4c)(+8r,+4c)
    const int lrow = (lane & 7) + ((lane >> 3) & 1) * 8;   // row within 16
    const int lcol = (lane >> 4) << 2;                     // 0 or 4
    const uint32_t aoff    = (uint32_t)(((wm + lrow) * 36 + lcol) * 4);
    const uint32_t boff_tb = (uint32_t)(((wn + (lane & 7)) * 36 + (((lane >> 3) & 1) << 2)) * 4);

    float acc[4][4][4];
    #pragma unroll
    for (int mi = 0; mi < 4; mi++)
        #pragma unroll
        for (int ni = 0; ni < 4; ni++)
            #pragma unroll
            for (int q = 0; q < 4; q++) acc[mi][ni][q] = 0.0f;

    int ar[4], ac[4], br[4], bc[4];
    #pragma unroll
    for (int u = 0; u < 4; u++) {
        int f = tid + u * 256;
        ar[u] = f >> 3; ac[u] = (f & 7) * 4;               // A: 128 rows x 8 chunks
        if (TB) { br[u] = f >> 3; bc[u] = (f & 7) * 4; }   // B: 128 rows x 8 chunks
        else    { br[u] = f >> 5; bc[u] = (f & 31) * 4; }  // B: 32 rows x 32 chunks
    }

    const int nk = K >> 5;

    // prologue: stage 0
    {
        #pragma unroll
        for (int u = 0; u < 4; u++)
            cpa16(sa + (uint32_t)(ar[u] * 36 + ac[u]) * 4,
                  &A[(size_t)(by + ar[u]) * K + ac[u]]);
        if (TB) {
            #pragma unroll
            for (int u = 0; u < 4; u++)
                cpa16(sb + (uint32_t)(br[u] * 36 + bc[u]) * 4,
                      &Bm[(size_t)(bx + br[u]) * K + bc[u]]);
        } else {
            #pragma unroll
            for (int u = 0; u < 4; u++)
                cpa16(sb + (uint32_t)(br[u] * 136 + bc[u]) * 4,
                      &Bm[(size_t)(br[u]) * N + bx + bc[u]]);
        }
        asm volatile("cp.async.commit_group;\n" ::);
    }

    for (int kt = 0; kt < nk; kt++) {
        const int p = kt & 1;
        if (kt + 1 < nk) {
            const int ko = (kt + 1) * 32;
            const uint32_t pa = sa + (uint32_t)(((kt + 1) & 1) * ASTG) * 4;
            const uint32_t pb = sb + (uint32_t)(((kt + 1) & 1) * BSTG) * 4;
            #pragma unroll
            for (int u = 0; u < 4; u++)
                cpa16(pa + (uint32_t)(ar[u] * 36 + ac[u]) * 4,
                      &A[(size_t)(by + ar[u]) * K + ko + ac[u]]);
            if (TB) {
                #pragma unroll
                for (int u = 0; u < 4; u++)
                    cpa16(pb + (uint32_t)(br[u] * 36 + bc[u]) * 4,
                          &Bm[(size_t)(bx + br[u]) * K + ko + bc[u]]);
            } else {
                #pragma unroll
                for (int u = 0; u < 4; u++)
                    cpa16(pb + (uint32_t)(br[u] * 136 + bc[u]) * 4,
                          &Bm[(size_t)(ko + br[u]) * N + bx + bc[u]]);
            }
            asm volatile("cp.async.commit_group;\n" ::);
            asm volatile("cp.async.wait_group 1;\n" ::);
        } else {
            asm volatile("cp.async.wait_group 0;\n" ::);
        }
        __syncthreads();

        const uint32_t pA = sa + (uint32_t)(p * ASTG) * 4 + aoff;
        const uint32_t pB = sb + (uint32_t)(p * BSTG) * 4;
        const float* Bp = Bs + p * BSTG;
        #pragma unroll
        for (int k8 = 0; k8 < 32; k8 += 8) {
            uint32_t af[4][4];
            #pragma unroll
            for (int mi = 0; mi < 4; mi++)
                ldsm4(af[mi], pA + (uint32_t)((mi * 16 * 36 + k8) * 4));
            #pragma unroll
            for (int ni = 0; ni < 4; ni++) {
                uint32_t b0, b1;
                if (TB) {
                    ldsm2(b0, b1, pB + boff_tb + (uint32_t)((ni * 8 * 36 + k8) * 4));
                } else {
                    const int c0 = wn + ni * 8 + g;
                    b0 = __float_as_uint(Bp[(k8 + tg) * 136 + c0]);
                    b1 = __float_as_uint(Bp[(k8 + 4 + tg) * 136 + c0]);
                }
                #pragma unroll
                for (int mi = 0; mi < 4; mi++) mma8(acc[mi][ni], af[mi], b0, b1);
            }
        }
        __syncthreads();
    }

    #pragma unroll
    for (int mi = 0; mi < 4; mi++) {
        const int r0 = by + wm + mi * 16 + g;
        #pragma unroll
        for (int ni = 0; ni < 4; ni++) {
            const int c0 = bx + wn + ni * 8 + 2 * tg;
            float v0 = acc[mi][ni][0], v1 = acc[mi][ni][1];
            float v2 = acc[mi][ni][2], v3 = acc[mi][ni][3];
            if (EPI != 0) {
                float bb0 = bias[c0], bb1 = bias[c0 + 1];
                v0 += bb0; v1 += bb1; v2 += bb0; v3 += bb1;
            }
            if (EPI == 1) {
                v0 = gelu_exact(v0); v1 = gelu_exact(v1);
                v2 = gelu_exact(v2); v3 = gelu_exact(v3);
            }
            if (RND) {
                v0 = tf32r(v0); v1 = tf32r(v1); v2 = tf32r(v2); v3 = tf32r(v3);
            }
            float2 w0; w0.x = v0; w0.y = v1;
            float2 w1; w1.x = v2; w1.y = v3;
            *(float2*)&C[(size_t)r0 * N + c0] = w0;
            *(float2*)&C[(size_t)(r0 + 8) * N + c0] = w1;
        }
    }
}

// ---------------- fused tensor-core flash attention (ldmatrix fragments) ----------------
#define AT_SMEM 107520
__global__ __launch_bounds__(256, 2)
void attn_fused(const float* __restrict__ qp, const float* __restrict__ kp,
                const float* __restrict__ vp, float* __restrict__ att,
                float* __restrict__ vatt)
{
    extern __shared__ float sh[];
    float* Qs   = sh;                    // [128][68]
    float* Ks   = sh + 128 * 68;         // [64][68]
    float* Vs   = Ks + 64 * 68;          // [64][68]
    float* Ps   = Vs + 64 * 68;          // [128][68]
    float* smP  = Ps + 128 * 68;         // [128][4]
    float* sm_m = smP + 512;             // [128]
    float* sm_il= sm_m + 128;            // [128]

    const int bh = blockIdx.x, b = bh >> 4, h = bh & 15;
    const int qt = 7 - blockIdx.y;
    const int qbase = qt * 128;
    const int tid = threadIdx.x;
    const int lane = tid & 31, warp = tid >> 5;
    const int wy = warp >> 1, wx = warp & 1;
    const int wm = wy * 32;
    const int g = lane >> 2, tg = lane & 3;
    const float scale = 1.0f / (8.0f + 1e-6f);

    const uint32_t sQ = (uint32_t)__cvta_generic_to_shared(Qs);
    const uint32_t sK = (uint32_t)__cvta_generic_to_shared(Ks);
    const uint32_t sP = (uint32_t)__cvta_generic_to_shared(Ps);
    // ldmatrix per-lane addressing (validated mapping, stride 68 floats = 272B, 16B-aligned)
    const int lrow = (lane & 7) + ((lane >> 3) & 1) * 8;
    const int lcol = (lane >> 4) << 2;
    const uint32_t qoff = (uint32_t)(((wm + lrow) * 68 + lcol) * 4);               // A frags
    const uint32_t koff = (uint32_t)(((wx * 32 + (lane & 7)) * 68 + (((lane >> 3) & 1) << 2)) * 4); // B frags

    const float* qg = qp + ((size_t)(b * Sz + qbase)) * Dz + h * 64;
    #pragma unroll
    for (int u = 0; u < 8; u++) {
        int f = tid + u * 256;
        int r = f >> 4, c4 = (f & 15) * 4;
        *(float4*)&Qs[r * 68 + c4] = *(const float4*)&qg[(size_t)r * Dz + c4];
    }

    float* ab = att + (size_t)bh * Sz * Sz;
    {
        float4 z; z.x = z.y = z.z = z.w = 0.0f;
        for (int j2 = 2 * qt + 2; j2 < 16; j2++) {
            const int kb = j2 * 64;
            #pragma unroll
            for (int u = 0; u < 8; u++) {
                int f = tid + u * 256;
                int r = f >> 4, c4 = (f & 15) * 4;
                *(float4*)&ab[(size_t)(qbase + r) * Sz + kb + c4] = z;
            }
        }
    }

    const int jmax = 2 * qt + 1;
    float run_m[4], run_l[4];
    #pragma unroll
    for (int s = 0; s < 4; s++) { run_m[s] = -1e30f; run_l[s] = 0.0f; }

    // ---------------- phase 1: softmax stats ----------------
    for (int jt = 0; jt <= jmax; jt++) {
        const int kbase = jt * 64;
        __syncthreads();
        const float* kg = kp + ((size_t)(b * Sz + kbase)) * Dz + h * 64;
        #pragma unroll
        for (int u = 0; u < 4; u++) {
            int f = tid + u * 256;
            int r = f >> 4, c4 = (f & 15) * 4;
            *(float4*)&Ks[r * 68 + c4] = *(const float4*)&kg[(size_t)r * Dz + c4];
        }
        __syncthreads();

        float sacc[2][4][4];
        #pragma unroll
        for (int mi = 0; mi < 2; mi++)
            #pragma unroll
            for (int ni = 0; ni < 4; ni++)
                #pragma unroll
                for (int q = 0; q < 4; q++) sacc[mi][ni][q] = 0.0f;

        #pragma unroll
        for (int k8 = 0; k8 < 64; k8 += 8) {
            uint32_t af[2][4];
            ldsm4(af[0], sQ + qoff + (uint32_t)(k8 * 4));
            ldsm4(af[1], sQ + qoff + (uint32_t)((16 * 68 + k8) * 4));
            #pragma unroll
            for (int ni = 0; ni < 4; ni++) {
                uint32_t b0, b1;
                ldsm2(b0, b1, sK + koff + (uint32_t)((ni * 8 * 68 + k8) * 4));
                mma8(sacc[0][ni], af[0], b0, b1);
                mma8(sacc[1][ni], af[1], b0, b1);
            }
        }

        const bool msk = (jt >= 2 * qt);
        #pragma unroll
        for (int mi = 0; mi < 2; mi++) {
            #pragma unroll
            for (int hf = 0; hf < 2; hf++) {
                const int s = mi * 2 + hf;
                const int rowg = qbase + wm + mi * 16 + hf * 8 + g;
                float vv[8];
                float lm = run_m[s];
                #pragma unroll
                for (int ni = 0; ni < 4; ni++) {
                    #pragma unroll
                    for (int q = 0; q < 2; q++) {
                        float sv = sacc[mi][ni][hf * 2 + q] * scale;
                        if (msk && (kbase + wx * 32 + ni * 8 + 2 * tg + q > rowg)) sv = -1e30f;
                        vv[ni * 2 + q] = sv;
                        lm = fmaxf(lm, sv);
                    }
                }
                float al = 0.0f;
                #pragma unroll
                for (int idx = 0; idx < 8; idx++) al += __expf(vv[idx] - lm);
                run_l[s] = run_l[s] * __expf(run_m[s] - lm) + al;
                run_m[s] = lm;
            }
        }
    }

    #pragma unroll
    for (int s = 0; s < 4; s++) {
        float m = run_m[s], l = run_l[s];
        #pragma unroll
        for (int mk = 1; mk < 4; mk <<= 1) {
            float om = __shfl_xor_sync(0xffffffffu, m, mk);
            float ol = __shfl_xor_sync(0xffffffffu, l, mk);
            float mn = fmaxf(m, om);
            l = l * __expf(m - mn) + ol * __expf(om - mn);
            m = mn;
        }
        run_m[s] = m; run_l[s] = l;
    }
    if (tg == 0) {
        #pragma unroll
        for (int s = 0; s < 4; s++) {
            int row = wm + (s >> 1) * 16 + (s & 1) * 8 + g;
            smP[row * 4 + wx * 2]     = run_m[s];
            smP[row * 4 + wx * 2 + 1] = run_l[s];
        }
    }
    __syncthreads();
    if (tid < 128) {
        float m0 = smP[tid * 4], l0 = smP[tid * 4 + 1];
        float m1 = smP[tid * 4 + 2], l1 = smP[tid * 4 + 3];
        float mn = fmaxf(m0, m1);
        float l = l0 * __expf(m0 - mn) + l1 * __expf(m1 - mn);
        sm_m[tid] = mn;
        sm_il[tid] = 1.0f / l;
    }
    __syncthreads();

    float m_s[4], il_s[4];
    #pragma unroll
    for (int s = 0; s < 4; s++) {
        int row = wm + (s >> 1) * 16 + (s & 1) * 8 + g;
        m_s[s] = sm_m[row];
        il_s[s] = sm_il[row];
    }

    float oacc[2][4][4];
    #pragma unroll
    for (int mi = 0; mi < 2; mi++)
        #pragma unroll
        for (int ni = 0; ni < 4; ni++)
            #pragma unroll
            for (int q = 0; q < 4; q++) oacc[mi][ni][q] = 0.0f;

    // ---------------- phase 2: P write + P@V ----------------
    for (int jt = 0; jt <= jmax; jt++) {
        const int kbase = jt * 64;
        __syncthreads();
        const float* kg = kp + ((size_t)(b * Sz + kbase)) * Dz + h * 64;
        const float* vg = vp + ((size_t)(b * Sz + kbase)) * Dz + h * 64;
        #pragma unroll
        for (int u = 0; u < 4; u++) {
            int f = tid + u * 256;
            int r = f >> 4, c4 = (f & 15) * 4;
            *(float4*)&Ks[r * 68 + c4] = *(const float4*)&kg[(size_t)r * Dz + c4];
            *(float4*)&Vs[r * 68 + c4] = *(const float4*)&vg[(size_t)r * Dz + c4];
        }
        __syncthreads();

        float sacc[2][4][4];
        #pragma unroll
        for (int mi = 0; mi < 2; mi++)
            #pragma unroll
            for (int ni = 0; ni < 4; ni++)
                #pragma unroll
                for (int q = 0; q < 4; q++) sacc[mi][ni][q] = 0.0f;

        #pragma unroll
        for (int k8 = 0; k8 < 64; k8 += 8) {
            uint32_t af[2][4];
            ldsm4(af[0], sQ + qoff + (uint32_t)(k8 * 4));
            ldsm4(af[1], sQ + qoff + (uint32_t)((16 * 68 + k8) * 4));
            #pragma unroll
            for (int ni = 0; ni < 4; ni++) {
                uint32_t b0, b1;
                ldsm2(b0, b1, sK + koff + (uint32_t)((ni * 8 * 68 + k8) * 4));
                mma8(sacc[0][ni], af[0], b0, b1);
                mma8(sacc[1][ni], af[1], b0, b1);
            }
        }

        const bool msk = (jt >= 2 * qt);
        #pragma unroll
        for (int mi = 0; mi < 2; mi++) {
            #pragma unroll
            for (int hf = 0; hf < 2; hf++) {
                const int s = mi * 2 + hf;
                const int rowl = wm + mi * 16 + hf * 8 + g;
                const int rowg = qbase + rowl;
                const float mm = m_s[s], il = il_s[s];
                #pragma unroll
                for (int ni = 0; ni < 4; ni++) {
                    const int col0 = kbase + wx * 32 + ni * 8 + 2 * tg;
                    float sv0 = sacc[mi][ni][hf * 2] * scale;
                    float sv1 = sacc[mi][ni][hf * 2 + 1] * scale;
                    float p0 = (msk && (col0 > rowg)) ? 0.0f : __expf(sv0 - mm) * il;
                    float p1 = (msk && (col0 + 1 > rowg)) ? 0.0f : __expf(sv1 - mm) * il;
                    float2 w; w.x = p0; w.y = p1;
                    *(float2*)&Ps[rowl * 68 + wx * 32 + ni * 8 + 2 * tg] = w;
                }
            }
        }
        __syncthreads();

        #pragma unroll
        for (int k8 = 0; k8 < 64; k8 += 8) {
            uint32_t pa[2][4];
            ldsm4(pa[0], sP + qoff + (uint32_t)(k8 * 4));
            ldsm4(pa[1], sP + qoff + (uint32_t)((16 * 68 + k8) * 4));
            #pragma unroll
            for (int mi = 0; mi < 2; mi++)
                #pragma unroll
                for (int j = 0; j < 4; j++)
                    pa[mi][j] = tf32u(pa[mi][j]);
            #pragma unroll
            for (int ni = 0; ni < 4; ni++) {
                const int c0 = wx * 32 + ni * 8 + g;
                uint32_t b0 = __float_as_uint(Vs[(k8 + tg) * 68 + c0]);
                uint32_t b1 = __float_as_uint(Vs[(k8 + 4 + tg) * 68 + c0]);
                mma8(oacc[0][ni], pa[0], b0, b1);
                mma8(oacc[1][ni], pa[1], b0, b1);
            }
        }

        #pragma unroll
        for (int u = 0; u < 8; u++) {
            int f = tid + u * 256;
            int r = f >> 4, c4 = (f & 15) * 4;
            *(float4*)&ab[(size_t)(qbase + r) * Sz + kbase + c4] = *(float4*)&Ps[r * 68 + c4];
        }
    }

    // write v_att rounded (feeds Wo GEMM which expects tf32 inputs)
    #pragma unroll
    for (int mi = 0; mi < 2; mi++) {
        const int r0 = qbase + wm + mi * 16 + g;
        #pragma unroll
        for (int ni = 0; ni < 4; ni++) {
            const int c = h * 64 + wx * 32 + ni * 8 + 2 * tg;
            float2 w0; w0.x = tf32r(oacc[mi][ni][0]); w0.y = tf32r(oacc[mi][ni][1]);
            float2 w1; w1.x = tf32r(oacc[mi][ni][2]); w1.y = tf32r(oacc[mi][ni][3]);
            *(float2*)&vatt[((size_t)(b * Sz + r0)) * Dz + c] = w0;
            *(float2*)&vatt[((size_t)(b * Sz + r0 + 8)) * Dz + c] = w1;
        }
    }
}

// ---------------- fused residual add + LayerNorm (single pass, shfl reduce) ----------------
__global__ __launch_bounds__(256)
void ln_add(const float* __restrict__ x, const float* __restrict__ y,
            const float* __restrict__ g, const float* __restrict__ bt,
            float* __restrict__ out, float* __restrict__ out_r)
{
    __shared__ float wsum[8], wsq[8];
    const int r = blockIdx.x, tid = threadIdx.x;
    const int lane = tid & 31, warp = tid >> 5;

    float4 x4 = *(const float4*)&x[(size_t)r * Dz + tid * 4];
    float4 y4 = *(const float4*)&y[(size_t)r * Dz + tid * 4];
    float t0 = x4.x + y4.x, t1 = x4.y + y4.y, t2 = x4.z + y4.z, t3 = x4.w + y4.w;

    float s = t0 + t1 + t2 + t3;
    float q = t0 * t0 + t1 * t1 + t2 * t2 + t3 * t3;
    #pragma unroll
    for (int m = 16; m > 0; m >>= 1) {
        s += __shfl_xor_sync(0xffffffffu, s, m);
        q += __shfl_xor_sync(0xffffffffu, q, m);
    }
    if (lane == 0) { wsum[warp] = s; wsq[warp] = q; }
    __syncthreads();
    if (tid < 32) {
        float s8 = (lane < 8) ? wsum[lane] : 0.0f;
        float q8 = (lane < 8) ? wsq[lane] : 0.0f;
        #pragma unroll
        for (int m = 4; m > 0; m >>= 1) {
            s8 += __shfl_xor_sync(0xffffffffu, s8, m);
            q8 += __shfl_xor_sync(0xffffffffu, q8, m);
        }
        if (lane == 0) { wsum[0] = s8; wsq[0] = q8; }
    }
    __syncthreads();

    const float mu = wsum[0] * (1.0f / Dz);
    const float var = wsq[0] * (1.0f / Dz) - mu * mu;
    const float rstd = rsqrtf(var + 1e-5f);

    float4 g4 = *(const float4*)&g[tid * 4];
    float4 b4 = *(const float4*)&bt[tid * 4];
    float4 o;
    o.x = g4.x * (t0 - mu) * rstd + b4.x;
    o.y = g4.y * (t1 - mu) * rstd + b4.y;
    o.z = g4.z * (t2 - mu) * rstd + b4.z;
    o.w = g4.w * (t3 - mu) * rstd + b4.w;
    *(float4*)&out[(size_t)r * Dz + tid * 4] = o;
    if (out_r) {
        float4 orr;
        orr.x = tf32r(o.x); orr.y = tf32r(o.y); orr.z = tf32r(o.z); orr.w = tf32r(o.w);
        *(float4*)&out_r[(size_t)r * Dz + tid * 4] = orr;
    }
}

// ---------------- host launcher ----------------
extern "C" void kernel_launch(void* const* d_in, const int* in_sizes, int n_in,
                              void* d_out, int out_size)
{
    const float* Q   = (const float*)d_in[0];
    const float* Kin = (const float*)d_in[1];
    const float* Vin = (const float*)d_in[2];
    const float* W_q = (const float*)d_in[4];
    const float* W_k = (const float*)d_in[5];
    const float* W_v = (const float*)d_in[6];
    const float* W_o = (const float*)d_in[7];
    const float* w1  = (const float*)d_in[8];
    const float* b1  = (const float*)d_in[9];
    const float* w2  = (const float*)d_in[10];
    const float* b2  = (const float*)d_in[11];
    const float* lng = (const float*)d_in[12];
    const float* lnb = (const float*)d_in[13];

    float *qp, *kp, *vp, *vattp, *Xp, *Xr, *Qr, *h1p, *tp, *wr, *attfb;
    cudaGetSymbolAddress((void**)&qp, g_q);
    cudaGetSymbolAddress((void**)&kp, g_k);
    cudaGetSymbolAddress((void**)&vp, g_v);
    cudaGetSymbolAddress((void**)&vattp, g_vatt);
    cudaGetSymbolAddress((void**)&Xp, g_X);
    cudaGetSymbolAddress((void**)&Xr, g_xr);
    cudaGetSymbolAddress((void**)&Qr, g_qr);
    cudaGetSymbolAddress((void**)&h1p, g_h1);
    cudaGetSymbolAddress((void**)&tp, g_t);
    cudaGetSymbolAddress((void**)&wr, g_wr);
    cudaGetSymbolAddress((void**)&attfb, g_attfb);

    float* wq_r = wr;
    float* wk_r = wr + 1 * (size_t)Dz * Dz;
    float* wv_r = wr + 2 * (size_t)Dz * Dz;
    float* wo_r = wr + 3 * (size_t)Dz * Dz;
    float* w1_r = wr + 4 * (size_t)Dz * Dz;
    float* w2_r = wr + 5 * (size_t)Dz * Dz;
    float* Kr = h1p;   // temp rounded K input (g_h1 free until FFN)
    float* Vr = tp;    // temp rounded V input (g_t free until Wo GEMM)

    const int SM_NN = 2 * (ASTG + 4352) * 4;   // 71680
    const int SM_NT = 2 * (ASTG + 4608) * 4;   // 73728
    cudaFuncSetAttribute(attn_fused, cudaFuncAttributeMaxDynamicSharedMemorySize, AT_SMEM);
    cudaFuncSetAttribute(tgemm2<false,0,true>,  cudaFuncAttributeMaxDynamicSharedMemorySize, SM_NN);
    cudaFuncSetAttribute(tgemm2<false,0,false>, cudaFuncAttributeMaxDynamicSharedMemorySize, SM_NN);
    cudaFuncSetAttribute(tgemm2<true,1,true>,   cudaFuncAttributeMaxDynamicSharedMemorySize, SM_NT);
    cudaFuncSetAttribute(tgemm2<true,2,false>,  cudaFuncAttributeMaxDynamicSharedMemorySize, SM_NT);

    const size_t OUT_MAIN = (size_t)Mz * Dz;            // 8388608
    const size_t ATT_N    = (size_t)BHz * Sz * Sz;      // 134217728
    float* outp = (float*)d_out;
    float* att  = ((size_t)out_size >= OUT_MAIN + ATT_N) ? (outp + OUT_MAIN) : attfb;

    dim3 gg(Dz / 128, Mz / 128);
    dim3 gb(256);
    dim3 ag(BHz, 8);
    const int M4 = (Mz * Dz) / 4, W4 = (Dz * Dz) / 4;

    // pre-round activations + weights once (semantically identical to per-tile cvt)
    roundcopy3<<<dim3(M4 / 256, 3), 256>>>(
        (const float4*)Q, (const float4*)Kin, (const float4*)Vin,
        (float4*)Qr, (float4*)Kr, (float4*)Vr);
    roundcopy6<<<dim3(W4 / 256, 6), 256>>>(
        (const float4*)W_q, (const float4*)W_k, (const float4*)W_v,
        (const float4*)W_o, (const float4*)w1, (const float4*)w2,
        (float4*)wr, W4);   // seg in float4 units

    // QKV projections
    tgemm2<false,0,true><<<gg, gb, SM_NN>>>(Qr, wq_r, nullptr, qp, Mz, Dz, Dz);
    tgemm2<false,0,true><<<gg, gb, SM_NN>>>(Kr, wk_r, nullptr, kp, Mz, Dz, Dz);
    tgemm2<false,0,true><<<gg, gb, SM_NN>>>(Vr, wv_r, nullptr, vp, Mz, Dz, Dz);
    // fused flash attention (vatt rounded in epilogue)
    attn_fused<<<ag, gb, AT_SMEM>>>(qp, kp, vp, att, vattp);
    // output projection + first residual LN (residual uses ORIGINAL Q)
    tgemm2<false,0,false><<<gg, gb, SM_NN>>>(vattp, wo_r, nullptr, tp, Mz, Dz, Dz);
    ln_add<<<Mz, 256>>>(Q, tp, lng, lnb, Xp, Xr);
    // FFN
    tgemm2<true,1,true><<<gg, gb, SM_NT>>>(Xr, w1_r, b1, h1p, Mz, Dz, Dz);
    tgemm2<true,2,false><<<gg, gb, SM_NT>>>(h1p, w2_r, b2, tp, Mz, Dz, Dz);
    // final residual LN -> d_out
    ln_add<<<Mz, 256>>>(Xp, tp, lng, lnb, outp, nullptr);
}